// round 1
// baseline (speedup 1.0000x reference)
#include <cuda_runtime.h>
#include <cuda_bf16.h>

// Problem constants
#define B_ 4
#define T_ 1024
#define C_ 1024
#define H_ 16
#define D_ 64
#define WMAX 80           // logits j >= 80 are exactly zero
#define MTOT (B_ * T_)    // 4096

// Scratch (allocation-free rule: __device__ globals)
static __device__ float g_qp[MTOT * C_];
static __device__ float g_kp[MTOT * C_];
static __device__ float g_vp[MTOT * C_];
static __device__ float g_o1[MTOT * C_];

// ---------------------------------------------------------------------------
// SGEMM (NT): C[m,n] = sum_k A[m,k] * W[n,k] (+ bias[n])
// Block tile 128x128, K-tile 8, 256 threads, 8x8 per-thread (split 4+4 to keep
// float4 smem loads conflict-free).
// ---------------------------------------------------------------------------
__global__ __launch_bounds__(256) void sgemm_nt(
    const float* __restrict__ A, const float* __restrict__ W,
    const float* __restrict__ bias, float* __restrict__ C,
    int M, int N, int K)
{
    __shared__ float As[8][128];
    __shared__ float Ws[8][128];

    const int tid  = threadIdx.x;
    const int bm   = blockIdx.y * 128;
    const int bn   = blockIdx.x * 128;
    const int lrow = tid >> 1;           // 0..127
    const int lcol = (tid & 1) << 2;     // 0 or 4
    const int ty   = tid >> 4;           // 0..15
    const int tx   = tid & 15;           // 0..15

    const float* Ap = A + (size_t)(bm + lrow) * K + lcol;
    const float* Bp = W + (size_t)(bn + lrow) * K + lcol;

    float acc[8][8];
#pragma unroll
    for (int i = 0; i < 8; i++)
#pragma unroll
        for (int j = 0; j < 8; j++) acc[i][j] = 0.f;

    for (int k0 = 0; k0 < K; k0 += 8) {
        float4 a4 = *(const float4*)(Ap + k0);
        float4 w4 = *(const float4*)(Bp + k0);
        As[lcol + 0][lrow] = a4.x; As[lcol + 1][lrow] = a4.y;
        As[lcol + 2][lrow] = a4.z; As[lcol + 3][lrow] = a4.w;
        Ws[lcol + 0][lrow] = w4.x; Ws[lcol + 1][lrow] = w4.y;
        Ws[lcol + 2][lrow] = w4.z; Ws[lcol + 3][lrow] = w4.w;
        __syncthreads();
#pragma unroll
        for (int kk = 0; kk < 8; kk++) {
            float ra[8], rb[8];
            *(float4*)&ra[0] = *(const float4*)&As[kk][ty * 4];
            *(float4*)&ra[4] = *(const float4*)&As[kk][ty * 4 + 64];
            *(float4*)&rb[0] = *(const float4*)&Ws[kk][tx * 4];
            *(float4*)&rb[4] = *(const float4*)&Ws[kk][tx * 4 + 64];
#pragma unroll
            for (int i = 0; i < 8; i++)
#pragma unroll
                for (int j = 0; j < 8; j++)
                    acc[i][j] = fmaf(ra[i], rb[j], acc[i][j]);
        }
        __syncthreads();
    }

    float4 b0 = make_float4(0.f, 0.f, 0.f, 0.f), b1 = b0;
    if (bias) {
        b0 = *(const float4*)(bias + bn + tx * 4);
        b1 = *(const float4*)(bias + bn + tx * 4 + 64);
    }

#pragma unroll
    for (int i = 0; i < 8; i++) {
        int row = bm + ((i < 4) ? (ty * 4 + i) : (64 + ty * 4 + (i - 4)));
        float* Cp = C + (size_t)row * N + bn;
        float4 v0, v1;
        v0.x = acc[i][0] + b0.x; v0.y = acc[i][1] + b0.y;
        v0.z = acc[i][2] + b0.z; v0.w = acc[i][3] + b0.w;
        v1.x = acc[i][4] + b1.x; v1.y = acc[i][5] + b1.y;
        v1.z = acc[i][6] + b1.z; v1.w = acc[i][7] + b1.w;
        *(float4*)(Cp + tx * 4)      = v0;
        *(float4*)(Cp + tx * 4 + 64) = v1;
    }
}

// ---------------------------------------------------------------------------
// Attention: per (b,h), logits row i = windowed partial-sums of qp[i]*kp[i]/8,
// nonzero only for j<80; the other 944 logits are exactly 0.
// out[i] = sum_{j<80} a_j * V[j] + (e^{-m}/Z) * sum_{j>=80} V[j]
// One warp per row i; V[0:80] and tail-sum S cached in smem per block.
// ---------------------------------------------------------------------------
__global__ __launch_bounds__(256) void attn_kernel(
    const float* __restrict__ qp, const float* __restrict__ kp,
    const float* __restrict__ vp, float* __restrict__ out)
{
    __shared__ float Vs[WMAX][D_];     // 20 KB
    __shared__ float Spart[4][D_];
    __shared__ float Ssum[D_];
    __shared__ float wbuf[8][WMAX];
    __shared__ float scs[8][68];       // cs[0..64] per warp

    const int tid   = threadIdx.x;
    const int lane  = tid & 31;
    const int w     = tid >> 5;        // warp 0..7
    const int chunk = blockIdx.x;      // 0..3  (rows i in chunks of 256)
    const int h     = blockIdx.y;
    const int b     = blockIdx.z;
    const size_t base = (size_t)b * T_ * C_ + (size_t)h * D_;

    // Load V[0:80][0:64] into smem
    for (int idx = tid; idx < WMAX * D_; idx += 256) {
        int j = idx >> 6, d = idx & 63;
        Vs[j][d] = vp[base + (size_t)j * C_ + d];
    }
    // S[d] = sum_{j=80..1023} V[j][d]  (4-way split over threads)
    {
        int d = tid & 63, part = tid >> 6;
        float s = 0.f;
        for (int j = WMAX + part; j < T_; j += 4)
            s += vp[base + (size_t)j * C_ + d];
        Spart[part][d] = s;
    }
    __syncthreads();
    if (tid < D_)
        Ssum[tid] = Spart[0][tid] + Spart[1][tid] + Spart[2][tid] + Spart[3][tid];
    __syncthreads();

    const float2 S2 = *(const float2*)&Ssum[lane * 2];

    for (int r = 0; r < 32; r++) {
        const int i = chunk * 256 + w * 32 + r;
        const float2 qv = *(const float2*)(qp + base + (size_t)i * C_ + lane * 2);
        const float2 kv = *(const float2*)(kp + base + (size_t)i * C_ + lane * 2);
        const float p0 = qv.x * kv.x * 0.125f;
        const float p1 = qv.y * kv.y * 0.125f;

        // warp-inclusive scan of pair sums
        float s = p0 + p1;
#pragma unroll
        for (int off = 1; off < 32; off <<= 1) {
            float t = __shfl_up_sync(0xffffffffu, s, off);
            if (lane >= off) s += t;
        }
        // cs[k] = sum of first k elements:  cs[2l+1]=incl[2l], cs[2l+2]=incl[2l+1]
        scs[w][2 * lane + 1] = s - p1;
        scs[w][2 * lane + 2] = s;
        if (lane == 0) scs[w][0] = 0.f;
        __syncwarp();

        // logits for j = lane, lane+32, lane+64
        float wjv[3];
        float m = 0.f;  // includes the 944 zero logits
#pragma unroll
        for (int t3 = 0; t3 < 3; t3++) {
            int j = lane + 32 * t3;
            float wv = -1e30f;
            if (j < WMAX) {
                int st = (j > 16) ? (j - 16) : 0;
                int en = (j + 16 < 64) ? (j + 16) : 64;
                wv = scs[w][en] - scs[w][st];
                m = fmaxf(m, wv);
            }
            wjv[t3] = wv;
        }
#pragma unroll
        for (int off = 16; off >= 1; off >>= 1)
            m = fmaxf(m, __shfl_xor_sync(0xffffffffu, m, off));

        float zs = 0.f;
#pragma unroll
        for (int t3 = 0; t3 < 3; t3++) {
            int j = lane + 32 * t3;
            if (j < WMAX) {
                float e = __expf(wjv[t3] - m);
                zs += e;
                wjv[t3] = e;
            }
        }
#pragma unroll
        for (int off = 16; off >= 1; off >>= 1)
            zs += __shfl_xor_sync(0xffffffffu, zs, off);

        const float em = __expf(-m);
        const float invZ = 1.0f / (zs + 944.0f * em);
#pragma unroll
        for (int t3 = 0; t3 < 3; t3++) {
            int j = lane + 32 * t3;
            if (j < WMAX) wbuf[w][j] = wjv[t3] * invZ;
        }
        __syncwarp();

        const float c = em * invZ;
        float2 acc = make_float2(c * S2.x, c * S2.y);
#pragma unroll
        for (int j = 0; j < WMAX; j++) {
            float aj = wbuf[w][j];
            float2 vv = *(const float2*)&Vs[j][lane * 2];
            acc.x = fmaf(aj, vv.x, acc.x);
            acc.y = fmaf(aj, vv.y, acc.y);
        }
        *(float2*)(out + base + (size_t)i * C_ + lane * 2) = acc;
        __syncwarp();   // protect scs/wbuf before next row's writes
    }
}

// ---------------------------------------------------------------------------
extern "C" void kernel_launch(void* const* d_in, const int* in_sizes, int n_in,
                              void* d_out, int out_size)
{
    const float* q  = (const float*)d_in[0];
    const float* k  = (const float*)d_in[1];
    const float* v  = (const float*)d_in[2];
    const float* Wq = (const float*)d_in[3];
    const float* Wk = (const float*)d_in[4];
    const float* Wv = (const float*)d_in[5];
    const float* Wp = (const float*)d_in[6];
    const float* bp = (const float*)d_in[7];
    float* out = (float*)d_out;

    float *qp, *kp, *vp, *o1;
    cudaGetSymbolAddress((void**)&qp, g_qp);
    cudaGetSymbolAddress((void**)&kp, g_kp);
    cudaGetSymbolAddress((void**)&vp, g_vp);
    cudaGetSymbolAddress((void**)&o1, g_o1);

    dim3 gg(C_ / 128, MTOT / 128);   // (8, 32)
    sgemm_nt<<<gg, 256>>>(q, Wq, nullptr, qp, MTOT, C_, C_);
    sgemm_nt<<<gg, 256>>>(k, Wk, nullptr, kp, MTOT, C_, C_);
    sgemm_nt<<<gg, 256>>>(v, Wv, nullptr, vp, MTOT, C_, C_);

    dim3 ga(T_ / 256, H_, B_);       // (4, 16, 4)
    attn_kernel<<<ga, 256>>>(qp, kp, vp, o1);

    sgemm_nt<<<gg, 256>>>(o1, Wp, bp, out, MTOT, C_, C_);
}

// round 3
// speedup vs baseline: 2.4667x; 2.4667x over previous
#include <cuda_runtime.h>
#include <cuda_bf16.h>
#include <cstdint>

// Problem constants
#define B_ 4
#define T_ 1024
#define C_ 1024
#define H_ 16
#define D_ 64
#define WMAX 80           // logits j >= 80 are exactly zero
#define MTOT (B_ * T_)    // 4096
#define K3 3072           // split-K: [hi, lo, hi] x [hi, hi, lo]
#define KT 48             // K3 / 64
#define STAGE_BYTES 32768 // A 16KB + B 16KB per stage
#define NSTAGE 3
#define GEMM_SMEM (NSTAGE * STAGE_BYTES)

// Scratch (allocation-free rule: __device__ globals)
static __device__ float g_qp[MTOT * C_];
static __device__ float g_kp[MTOT * C_];
static __device__ float g_vp[MTOT * C_];
static __device__ float g_o1[MTOT * C_];
static __device__ __align__(16) __nv_bfloat16 g_a3[MTOT * K3];  // 24 MB
static __device__ __align__(16) __nv_bfloat16 g_w3[C_ * K3];    // 6 MB

// ---------------------------------------------------------------------------
// PTX helpers (plain sm_103-safe: no tcgen05 / 'a'-gated features)
// ---------------------------------------------------------------------------
__device__ __forceinline__ uint32_t smem_u32(const void* p) {
    uint32_t a;
    asm("{ .reg .u64 t; cvta.to.shared.u64 t, %1; cvt.u32.u64 %0, t; }" : "=r"(a) : "l"(p));
    return a;
}
__device__ __forceinline__ void cp16(uint32_t dst, const void* src) {
    asm volatile("cp.async.cg.shared.global [%0], [%1], 16;" :: "r"(dst), "l"(src));
}
#define CP_COMMIT() asm volatile("cp.async.commit_group;" ::: "memory")
#define CP_WAIT(n)  asm volatile("cp.async.wait_group %0;" :: "n"(n) : "memory")

#define LDSM4(r0, r1, r2, r3, addr) \
    asm volatile("ldmatrix.sync.aligned.m8n8.x4.shared.b16 {%0,%1,%2,%3}, [%4];" \
                 : "=r"(r0), "=r"(r1), "=r"(r2), "=r"(r3) : "r"(addr))

#define MMA_BF16(d, a, b0, b1) \
    asm volatile("mma.sync.aligned.m16n8k16.row.col.f32.bf16.bf16.f32 " \
                 "{%0,%1,%2,%3},{%4,%5,%6,%7},{%8,%9},{%0,%1,%2,%3};" \
                 : "+f"((d)[0]), "+f"((d)[1]), "+f"((d)[2]), "+f"((d)[3]) \
                 : "r"((a)[0]), "r"((a)[1]), "r"((a)[2]), "r"((a)[3]), \
                   "r"(b0), "r"(b1))

__device__ __forceinline__ uint32_t swz(uint32_t off) {   // SW128
    return off ^ ((off >> 3) & 0x70);
}

// ---------------------------------------------------------------------------
// Split fp32 -> bf16 triple layout: dst row pitch K3.
//   writes hi at col+0 and col+offDup, lo at col+offLo
//   activations: offDup=2048, offLo=1024  -> [Ah, Al, Ah]
//   weights:     offDup=1024, offLo=2048  -> [Wh, Wh, Wl]
// ---------------------------------------------------------------------------
__global__ __launch_bounds__(256) void split3_kernel(
    const float* __restrict__ x, __nv_bfloat16* __restrict__ dst,
    int n4, int offDup, int offLo)
{
    int i = blockIdx.x * 256 + threadIdx.x;
    if (i >= n4) return;
    float4 v = ((const float4*)x)[i];
    __nv_bfloat16 h0 = __float2bfloat16(v.x);
    __nv_bfloat16 h1 = __float2bfloat16(v.y);
    __nv_bfloat16 h2 = __float2bfloat16(v.z);
    __nv_bfloat16 h3 = __float2bfloat16(v.w);
    __nv_bfloat16 l0 = __float2bfloat16(v.x - __bfloat162float(h0));
    __nv_bfloat16 l1 = __float2bfloat16(v.y - __bfloat162float(h1));
    __nv_bfloat16 l2 = __float2bfloat16(v.z - __bfloat162float(h2));
    __nv_bfloat16 l3 = __float2bfloat16(v.w - __bfloat162float(h3));
    uint2 ph, pl;
    ph.x = ((uint32_t)__bfloat16_as_ushort(h1) << 16) | __bfloat16_as_ushort(h0);
    ph.y = ((uint32_t)__bfloat16_as_ushort(h3) << 16) | __bfloat16_as_ushort(h2);
    pl.x = ((uint32_t)__bfloat16_as_ushort(l1) << 16) | __bfloat16_as_ushort(l0);
    pl.y = ((uint32_t)__bfloat16_as_ushort(l3) << 16) | __bfloat16_as_ushort(l2);
    int m   = i >> 8;            // 256 float4 per source row (C_=1024)
    int col = (i & 255) * 4;
    size_t base = (size_t)m * K3 + col;
    *(uint2*)(dst + base)          = ph;
    *(uint2*)(dst + base + offDup) = ph;
    *(uint2*)(dst + base + offLo)  = pl;
}

// ---------------------------------------------------------------------------
// bf16 NT GEMM via mma.sync m16n8k16: C[m,n] = sum_k A3[m,k]*W3[n,k] (+bias)
// M=4096, N=1024, K=3072. CTA 128x128, 8 warps (2x4), warp tile 64x32.
// SW128-swizzled smem, 3-stage cp.async pipeline, K-tile 64.
// ---------------------------------------------------------------------------
__global__ __launch_bounds__(256, 2) void gemm_bf16s(
    const __nv_bfloat16* __restrict__ A3, const __nv_bfloat16* __restrict__ W3,
    const float* __restrict__ bias, float* __restrict__ Cout)
{
    extern __shared__ char smem[];
    const uint32_t sb = smem_u32(smem);
    const int tid  = threadIdx.x;
    const int lane = tid & 31;
    const int wid  = tid >> 5;
    const int bm   = blockIdx.y * 128;
    const int bn   = blockIdx.x * 128;
    const int wm   = (wid >> 2) * 64;   // warp M offset (0/64)
    const int wn   = (wid & 3) * 32;    // warp N offset

    float acc[4][4][4];
#pragma unroll
    for (int i = 0; i < 4; i++)
#pragma unroll
        for (int j = 0; j < 4; j++)
#pragma unroll
            for (int c = 0; c < 4; c++) acc[i][j][c] = 0.f;

    auto issue = [&](int stage, int kt) {
        const int k0 = kt * 64;
#pragma unroll
        for (int it = 0; it < 8; it++) {
            int idx = tid + it * 256;          // 0..2047
            int isB = idx >= 1024;
            int l   = idx & 1023;
            int row = l >> 3, ch = l & 7;
            const __nv_bfloat16* src =
                (isB ? W3 + (size_t)(bn + row) * K3 : A3 + (size_t)(bm + row) * K3)
                + k0 + ch * 8;
            uint32_t off = (uint32_t)row * 128 + ch * 16;
            uint32_t dst = sb + stage * STAGE_BYTES + (isB ? 16384 : 0) + swz(off);
            cp16(dst, src);
        }
    };

    issue(0, 0); CP_COMMIT();
    issue(1, 1); CP_COMMIT();

    // ldmatrix per-lane address components
    const uint32_t rA = wm + (lane & 7) + ((lane >> 3) & 1) * 8;
    const uint32_t kA = ((lane >> 4) & 1) * 16;                  // bytes
    const uint32_t rB = wn + (lane & 7) + ((lane >> 4) & 1) * 8;
    const uint32_t kB = ((lane >> 3) & 1) * 16;                  // bytes

#pragma unroll 1
    for (int kt = 0; kt < KT; kt++) {
        CP_WAIT(1);
        __syncthreads();
        if (kt + 2 < KT) issue((kt + 2) % NSTAGE, kt + 2);
        CP_COMMIT();

        const uint32_t sA = sb + (kt % NSTAGE) * STAGE_BYTES;
        const uint32_t sB = sA + 16384;
#pragma unroll
        for (int ks = 0; ks < 4; ks++) {
            uint32_t a[4][4], b[2][4];
#pragma unroll
            for (int ti = 0; ti < 4; ti++) {
                uint32_t off = (rA + ti * 16) * 128 + ks * 32 + kA;
                LDSM4(a[ti][0], a[ti][1], a[ti][2], a[ti][3], sA + swz(off));
            }
#pragma unroll
            for (int tp = 0; tp < 2; tp++) {
                uint32_t off = (rB + tp * 16) * 128 + ks * 32 + kB;
                LDSM4(b[tp][0], b[tp][1], b[tp][2], b[tp][3], sB + swz(off));
            }
#pragma unroll
            for (int ti = 0; ti < 4; ti++)
#pragma unroll
                for (int tj = 0; tj < 4; tj++)
                    MMA_BF16(acc[ti][tj], a[ti], b[tj >> 1][(tj & 1) * 2],
                             b[tj >> 1][(tj & 1) * 2 + 1]);
        }
    }

    // Epilogue
    const int col0 = bn + wn + (lane & 3) * 2;
    const int r0   = lane >> 2;
    float2 bv[4];
#pragma unroll
    for (int tj = 0; tj < 4; tj++)
        bv[tj] = bias ? *(const float2*)(bias + col0 + tj * 8)
                      : make_float2(0.f, 0.f);
#pragma unroll
    for (int ti = 0; ti < 4; ti++) {
        const int row = bm + wm + ti * 16 + r0;
#pragma unroll
        for (int tj = 0; tj < 4; tj++) {
            float2 v0 = make_float2(acc[ti][tj][0] + bv[tj].x,
                                    acc[ti][tj][1] + bv[tj].y);
            float2 v1 = make_float2(acc[ti][tj][2] + bv[tj].x,
                                    acc[ti][tj][3] + bv[tj].y);
            *(float2*)(Cout + (size_t)row * C_ + col0 + tj * 8)       = v0;
            *(float2*)(Cout + (size_t)(row + 8) * C_ + col0 + tj * 8) = v1;
        }
    }
}

// ---------------------------------------------------------------------------
// Attention: logits nonzero only for j<80; 944 tail logits are exactly 0.
// out[i] = sum_{j<80} a_j * V[j] + (e^{-m}/Z) * sum_{j>=80} V[j]
// 1 warp = 32 rows processed as 8 quads of 4 (4x less smem traffic in AV loop)
// ---------------------------------------------------------------------------
__global__ __launch_bounds__(256) void attn_kernel(
    const float* __restrict__ qp, const float* __restrict__ kp,
    const float* __restrict__ vp, float* __restrict__ out)
{
    __shared__ float Vs[WMAX][D_];       // 20 KB
    __shared__ float Spart[4][D_];
    __shared__ float Ssum[D_];
    __shared__ float wbuf[8][4][WMAX];   // 10 KB
    __shared__ float scs[8][4][68];      // 8.5 KB

    const int tid   = threadIdx.x;
    const int lane  = tid & 31;
    const int w     = tid >> 5;
    const int chunk = blockIdx.x;        // 0..3
    const int h     = blockIdx.y;
    const int b     = blockIdx.z;
    const size_t base = (size_t)b * T_ * C_ + (size_t)h * D_;

    for (int idx = tid; idx < WMAX * D_; idx += 256) {
        int j = idx >> 6, d = idx & 63;
        Vs[j][d] = vp[base + (size_t)j * C_ + d];
    }
    {
        int d = tid & 63, part = tid >> 6;
        float s = 0.f;
        for (int j = WMAX + part; j < T_; j += 4)
            s += vp[base + (size_t)j * C_ + d];
        Spart[part][d] = s;
    }
    __syncthreads();
    if (tid < D_)
        Ssum[tid] = Spart[0][tid] + Spart[1][tid] + Spart[2][tid] + Spart[3][tid];
    __syncthreads();

    const float2 S2 = *(const float2*)&Ssum[lane * 2];

    for (int rq = 0; rq < 8; rq++) {
        const int ibase = chunk * 256 + w * 32 + rq * 4;
        float cr[4];
#pragma unroll
        for (int rr = 0; rr < 4; rr++) {
            const int i = ibase + rr;
            const float2 qv = *(const float2*)(qp + base + (size_t)i * C_ + lane * 2);
            const float2 kv = *(const float2*)(kp + base + (size_t)i * C_ + lane * 2);
            const float p0 = qv.x * kv.x * 0.125f;
            const float p1 = qv.y * kv.y * 0.125f;

            float s = p0 + p1;
#pragma unroll
            for (int off = 1; off < 32; off <<= 1) {
                float t = __shfl_up_sync(0xffffffffu, s, off);
                if (lane >= off) s += t;
            }
            scs[w][rr][2 * lane + 1] = s - p1;
            scs[w][rr][2 * lane + 2] = s;
            if (lane == 0) scs[w][rr][0] = 0.f;
            __syncwarp();

            float wjv[3];
            float m = 0.f;   // includes the 944 exact-zero logits
#pragma unroll
            for (int t3 = 0; t3 < 3; t3++) {
                int j = lane + 32 * t3;
                float wv = -1e30f;
                if (j < WMAX) {
                    int st = (j > 16) ? (j - 16) : 0;
                    int en = (j + 16 < 64) ? (j + 16) : 64;
                    wv = scs[w][rr][en] - scs[w][rr][st];
                    m = fmaxf(m, wv);
                }
                wjv[t3] = wv;
            }
#pragma unroll
            for (int off = 16; off >= 1; off >>= 1)
                m = fmaxf(m, __shfl_xor_sync(0xffffffffu, m, off));

            float zs = 0.f;
#pragma unroll
            for (int t3 = 0; t3 < 3; t3++) {
                int j = lane + 32 * t3;
                if (j < WMAX) {
                    float e = __expf(wjv[t3] - m);
                    zs += e;
                    wjv[t3] = e;
                }
            }
#pragma unroll
            for (int off = 16; off >= 1; off >>= 1)
                zs += __shfl_xor_sync(0xffffffffu, zs, off);

            const float em   = __expf(-m);
            const float invZ = 1.0f / (zs + 944.0f * em);
#pragma unroll
            for (int t3 = 0; t3 < 3; t3++) {
                int j = lane + 32 * t3;
                if (j < WMAX) wbuf[w][rr][j] = wjv[t3] * invZ;
            }
            cr[rr] = em * invZ;
            __syncwarp();
        }

        float2 acc[4];
#pragma unroll
        for (int rr = 0; rr < 4; rr++)
            acc[rr] = make_float2(cr[rr] * S2.x, cr[rr] * S2.y);
#pragma unroll 4
        for (int j = 0; j < WMAX; j++) {
            const float2 vv = *(const float2*)&Vs[j][lane * 2];
#pragma unroll
            for (int rr = 0; rr < 4; rr++) {
                const float aj = wbuf[w][rr][j];
                acc[rr].x = fmaf(aj, vv.x, acc[rr].x);
                acc[rr].y = fmaf(aj, vv.y, acc[rr].y);
            }
        }
#pragma unroll
        for (int rr = 0; rr < 4; rr++)
            *(float2*)(out + base + (size_t)(ibase + rr) * C_ + lane * 2) = acc[rr];
        __syncwarp();
    }
}

// ---------------------------------------------------------------------------
extern "C" void kernel_launch(void* const* d_in, const int* in_sizes, int n_in,
                              void* d_out, int out_size)
{
    const float* q  = (const float*)d_in[0];
    const float* k  = (const float*)d_in[1];
    const float* v  = (const float*)d_in[2];
    const float* Wq = (const float*)d_in[3];
    const float* Wk = (const float*)d_in[4];
    const float* Wv = (const float*)d_in[5];
    const float* Wp = (const float*)d_in[6];
    const float* bp = (const float*)d_in[7];
    float* out = (float*)d_out;

    float *qp, *kp, *vp, *o1;
    __nv_bfloat16 *a3, *w3;
    cudaGetSymbolAddress((void**)&qp, g_qp);
    cudaGetSymbolAddress((void**)&kp, g_kp);
    cudaGetSymbolAddress((void**)&vp, g_vp);
    cudaGetSymbolAddress((void**)&o1, g_o1);
    cudaGetSymbolAddress((void**)&a3, g_a3);
    cudaGetSymbolAddress((void**)&w3, g_w3);

    cudaFuncSetAttribute(gemm_bf16s, cudaFuncAttributeMaxDynamicSharedMemorySize, GEMM_SMEM);

    const int nA4 = MTOT * C_ / 4;   // 1,048,576
    const int nW4 = C_ * C_ / 4;     // 262,144
    dim3 gg(C_ / 128, MTOT / 128);   // (8, 32)
    dim3 ga(T_ / 256, H_, B_);       // (4, 16, 4)

    // Q projection
    split3_kernel<<<nA4 / 256, 256>>>(q, a3, nA4, 2048, 1024);
    split3_kernel<<<nW4 / 256, 256>>>(Wq, w3, nW4, 1024, 2048);
    gemm_bf16s<<<gg, 256, GEMM_SMEM>>>(a3, w3, nullptr, qp);
    // K projection
    split3_kernel<<<nA4 / 256, 256>>>(k, a3, nA4, 2048, 1024);
    split3_kernel<<<nW4 / 256, 256>>>(Wk, w3, nW4, 1024, 2048);
    gemm_bf16s<<<gg, 256, GEMM_SMEM>>>(a3, w3, nullptr, kp);
    // V projection
    split3_kernel<<<nA4 / 256, 256>>>(v, a3, nA4, 2048, 1024);
    split3_kernel<<<nW4 / 256, 256>>>(Wv, w3, nW4, 1024, 2048);
    gemm_bf16s<<<gg, 256, GEMM_SMEM>>>(a3, w3, nullptr, vp);

    attn_kernel<<<ga, 256>>>(qp, kp, vp, o1);

    // Output projection (+bias)
    split3_kernel<<<nA4 / 256, 256>>>(o1, a3, nA4, 2048, 1024);
    split3_kernel<<<nW4 / 256, 256>>>(Wp, w3, nW4, 1024, 2048);
    gemm_bf16s<<<gg, 256, GEMM_SMEM>>>(a3, w3, bp, out);
}

// round 4
// speedup vs baseline: 2.9257x; 1.1861x over previous
#include <cuda_runtime.h>
#include <cuda_fp16.h>
#include <cstdint>

// Problem constants
#define B_ 4
#define T_ 1024
#define C_ 1024
#define H_ 16
#define D_ 64
#define WMAX 80           // logits j >= 80 are exactly zero
#define MTOT (B_ * T_)    // 4096
#define KP 3072           // buffer pitch (max split-K)
#define STAGE_BYTES 49152 // A 16KB + B 32KB per stage
#define NSTAGE 4
#define GEMM_SMEM (NSTAGE * STAGE_BYTES)   // 196608

// Scratch (allocation-free rule: __device__ globals)
static __device__ float g_qp[MTOT * C_];
static __device__ float g_kp[MTOT * C_];
static __device__ float g_vp[MTOT * C_];
static __device__ float g_o1[MTOT * C_];
static __device__ __align__(16) __half g_a3[MTOT * KP];  // 24 MB
static __device__ __align__(16) __half g_w3[C_ * KP];    // 6 MB

// ---------------------------------------------------------------------------
// PTX helpers (plain sm_103-safe)
// ---------------------------------------------------------------------------
__device__ __forceinline__ uint32_t smem_u32(const void* p) {
    uint32_t a;
    asm("{ .reg .u64 t; cvta.to.shared.u64 t, %1; cvt.u32.u64 %0, t; }" : "=r"(a) : "l"(p));
    return a;
}
__device__ __forceinline__ void cp16(uint32_t dst, const void* src) {
    asm volatile("cp.async.cg.shared.global [%0], [%1], 16;" :: "r"(dst), "l"(src));
}
#define CP_COMMIT() asm volatile("cp.async.commit_group;" ::: "memory")
#define CP_WAIT(n)  asm volatile("cp.async.wait_group %0;" :: "n"(n) : "memory")

#define LDSM4(r0, r1, r2, r3, addr) \
    asm volatile("ldmatrix.sync.aligned.m8n8.x4.shared.b16 {%0,%1,%2,%3}, [%4];" \
                 : "=r"(r0), "=r"(r1), "=r"(r2), "=r"(r3) : "r"(addr))

#define MMA_F16(d, a, b0, b1) \
    asm volatile("mma.sync.aligned.m16n8k16.row.col.f32.f16.f16.f32 " \
                 "{%0,%1,%2,%3},{%4,%5,%6,%7},{%8,%9},{%0,%1,%2,%3};" \
                 : "+f"((d)[0]), "+f"((d)[1]), "+f"((d)[2]), "+f"((d)[3]) \
                 : "r"((a)[0]), "r"((a)[1]), "r"((a)[2]), "r"((a)[3]), \
                   "r"(b0), "r"(b1))

__device__ __forceinline__ uint32_t swz(uint32_t off) {   // SW128
    return off ^ ((off >> 3) & 0x70);
}

// ---------------------------------------------------------------------------
// Split fp32 -> fp16 multi-block layout, dst row pitch KP (=3072).
//   hi written at col+0; if dupOff>=0 hi also at col+dupOff;
//   if loOff>=0 lo at col+loOff.
//   act 2-term: (dup=-1, lo=1024)   -> [Ah, Al, -]
//   wgt 2-term: (dup=1024, lo=-1)   -> [Wh, Wh, -]
//   act 3-term: (dup=2048, lo=1024) -> [Ah, Al, Ah]
//   wgt 3-term: (dup=1024, lo=2048) -> [Wh, Wh, Wl]
// ---------------------------------------------------------------------------
__global__ __launch_bounds__(256) void splitk_kernel(
    const float* __restrict__ x, __half* __restrict__ dst,
    int n4, int dupOff, int loOff)
{
    int i = blockIdx.x * 256 + threadIdx.x;
    if (i >= n4) return;
    float4 v = ((const float4*)x)[i];
    __half h0 = __float2half_rn(v.x);
    __half h1 = __float2half_rn(v.y);
    __half h2 = __float2half_rn(v.z);
    __half h3 = __float2half_rn(v.w);
    uint2 ph;
    ph.x = ((uint32_t)__half_as_ushort(h1) << 16) | __half_as_ushort(h0);
    ph.y = ((uint32_t)__half_as_ushort(h3) << 16) | __half_as_ushort(h2);
    int m   = i >> 8;            // 256 float4 per source row (C_=1024)
    int col = (i & 255) * 4;
    size_t base = (size_t)m * KP + col;
    *(uint2*)(dst + base) = ph;
    if (dupOff >= 0) *(uint2*)(dst + base + dupOff) = ph;
    if (loOff >= 0) {
        __half l0 = __float2half_rn(v.x - __half2float(h0));
        __half l1 = __float2half_rn(v.y - __half2float(h1));
        __half l2 = __float2half_rn(v.z - __half2float(h2));
        __half l3 = __float2half_rn(v.w - __half2float(h3));
        uint2 pl;
        pl.x = ((uint32_t)__half_as_ushort(l1) << 16) | __half_as_ushort(l0);
        pl.y = ((uint32_t)__half_as_ushort(l3) << 16) | __half_as_ushort(l2);
        *(uint2*)(dst + base + loOff) = pl;
    }
}

// ---------------------------------------------------------------------------
// fp16 NT GEMM via mma.sync m16n8k16: C[m,n] = sum_k A[m,k]*W[n,k] (+bias)
// M=4096, N=1024, K = KT*64 (runtime). CTA 128x256, 8 warps (2x4),
// warp tile 64x64. SW128 smem, 4-stage cp.async pipeline, K-tile 64.
// Buffers have fixed row pitch KP.
// ---------------------------------------------------------------------------
__global__ __launch_bounds__(256, 1) void gemm_f16s(
    const __half* __restrict__ A3, const __half* __restrict__ W3,
    const float* __restrict__ bias, float* __restrict__ Cout, int KT)
{
    extern __shared__ char smem[];
    const uint32_t sb = smem_u32(smem);
    const int tid  = threadIdx.x;
    const int lane = tid & 31;
    const int wid  = tid >> 5;
    const int bm   = blockIdx.y * 128;
    const int bn   = blockIdx.x * 256;
    const int wm   = (wid >> 2) * 64;   // warp M offset (0/64)
    const int wn   = (wid & 3) * 64;    // warp N offset (0/64/128/192)

    float acc[4][8][4];
#pragma unroll
    for (int i = 0; i < 4; i++)
#pragma unroll
        for (int j = 0; j < 8; j++)
#pragma unroll
            for (int c = 0; c < 4; c++) acc[i][j][c] = 0.f;

    // per-stage: A 128 rows (16 KB) then B 256 rows (32 KB), 128B/row, SW128
    auto issue = [&](int kt) {
        const int stage = kt & (NSTAGE - 1);
        const int k0 = kt * 64;
#pragma unroll
        for (int it = 0; it < 12; it++) {
            int idx = tid + it * 256;          // 0..3071
            int isB = idx >= 1024;
            int l   = isB ? (idx - 1024) : idx;
            int row = l >> 3, ch = l & 7;
            const __half* src =
                (isB ? W3 + (size_t)(bn + row) * KP : A3 + (size_t)(bm + row) * KP)
                + k0 + ch * 8;
            uint32_t off = (uint32_t)row * 128 + ch * 16;
            uint32_t dst = sb + stage * STAGE_BYTES + (isB ? 16384 : 0) + swz(off);
            cp16(dst, src);
        }
    };

    issue(0); CP_COMMIT();
    issue(1); CP_COMMIT();
    issue(2); CP_COMMIT();

    // ldmatrix per-lane address components
    const uint32_t rA = wm + (lane & 7) + ((lane >> 3) & 1) * 8;
    const uint32_t kA = ((lane >> 4) & 1) * 16;                  // bytes
    const uint32_t rB = wn + (lane & 7) + ((lane >> 4) & 1) * 8;
    const uint32_t kB = ((lane >> 3) & 1) * 16;                  // bytes

#pragma unroll 1
    for (int kt = 0; kt < KT; kt++) {
        CP_WAIT(2);
        __syncthreads();
        if (kt + 3 < KT) issue(kt + 3);
        CP_COMMIT();

        const uint32_t sA = sb + (kt & (NSTAGE - 1)) * STAGE_BYTES;
        const uint32_t sB = sA + 16384;
#pragma unroll
        for (int ks = 0; ks < 4; ks++) {
            uint32_t a[4][4], b[4][4];
#pragma unroll
            for (int ti = 0; ti < 4; ti++) {
                uint32_t off = (rA + ti * 16) * 128 + ks * 32 + kA;
                LDSM4(a[ti][0], a[ti][1], a[ti][2], a[ti][3], sA + swz(off));
            }
#pragma unroll
            for (int tp = 0; tp < 4; tp++) {
                uint32_t off = (rB + tp * 16) * 128 + ks * 32 + kB;
                LDSM4(b[tp][0], b[tp][1], b[tp][2], b[tp][3], sB + swz(off));
            }
#pragma unroll
            for (int ti = 0; ti < 4; ti++)
#pragma unroll
                for (int tj = 0; tj < 8; tj++)
                    MMA_F16(acc[ti][tj], a[ti], b[tj >> 1][(tj & 1) * 2],
                            b[tj >> 1][(tj & 1) * 2 + 1]);
        }
    }

    // Epilogue
    const int col0 = bn + wn + (lane & 3) * 2;
    const int r0   = lane >> 2;
#pragma unroll
    for (int ti = 0; ti < 4; ti++) {
        const int row = bm + wm + ti * 16 + r0;
#pragma unroll
        for (int tj = 0; tj < 8; tj++) {
            float2 bv = bias ? *(const float2*)(bias + col0 + tj * 8)
                             : make_float2(0.f, 0.f);
            float2 v0 = make_float2(acc[ti][tj][0] + bv.x, acc[ti][tj][1] + bv.y);
            float2 v1 = make_float2(acc[ti][tj][2] + bv.x, acc[ti][tj][3] + bv.y);
            *(float2*)(Cout + (size_t)row * C_ + col0 + tj * 8)       = v0;
            *(float2*)(Cout + (size_t)(row + 8) * C_ + col0 + tj * 8) = v1;
        }
    }
}

// ---------------------------------------------------------------------------
// Attention: logits nonzero only for j<80; 944 tail logits are exactly 0.
// out[i] = sum_{j<80} a_j * V[j] + (e^{-m}/Z) * sum_{j>=80} V[j]
// 1 warp = 32 rows processed as 8 quads of 4 (4x less smem traffic in AV loop)
// ---------------------------------------------------------------------------
__global__ __launch_bounds__(256) void attn_kernel(
    const float* __restrict__ qp, const float* __restrict__ kp,
    const float* __restrict__ vp, float* __restrict__ out)
{
    __shared__ float Vs[WMAX][D_];       // 20 KB
    __shared__ float Spart[4][D_];
    __shared__ float Ssum[D_];
    __shared__ float wbuf[8][4][WMAX];   // 10 KB
    __shared__ float scs[8][4][68];      // 8.5 KB

    const int tid   = threadIdx.x;
    const int lane  = tid & 31;
    const int w     = tid >> 5;
    const int chunk = blockIdx.x;        // 0..3
    const int h     = blockIdx.y;
    const int b     = blockIdx.z;
    const size_t base = (size_t)b * T_ * C_ + (size_t)h * D_;

    for (int idx = tid; idx < WMAX * D_; idx += 256) {
        int j = idx >> 6, d = idx & 63;
        Vs[j][d] = vp[base + (size_t)j * C_ + d];
    }
    {
        int d = tid & 63, part = tid >> 6;
        float s = 0.f;
        for (int j = WMAX + part; j < T_; j += 4)
            s += vp[base + (size_t)j * C_ + d];
        Spart[part][d] = s;
    }
    __syncthreads();
    if (tid < D_)
        Ssum[tid] = Spart[0][tid] + Spart[1][tid] + Spart[2][tid] + Spart[3][tid];
    __syncthreads();

    const float2 S2 = *(const float2*)&Ssum[lane * 2];

    for (int rq = 0; rq < 8; rq++) {
        const int ibase = chunk * 256 + w * 32 + rq * 4;
        float cr[4];
#pragma unroll
        for (int rr = 0; rr < 4; rr++) {
            const int i = ibase + rr;
            const float2 qv = *(const float2*)(qp + base + (size_t)i * C_ + lane * 2);
            const float2 kv = *(const float2*)(kp + base + (size_t)i * C_ + lane * 2);
            const float p0 = qv.x * kv.x * 0.125f;
            const float p1 = qv.y * kv.y * 0.125f;

            float s = p0 + p1;
#pragma unroll
            for (int off = 1; off < 32; off <<= 1) {
                float t = __shfl_up_sync(0xffffffffu, s, off);
                if (lane >= off) s += t;
            }
            scs[w][rr][2 * lane + 1] = s - p1;
            scs[w][rr][2 * lane + 2] = s;
            if (lane == 0) scs[w][rr][0] = 0.f;
            __syncwarp();

            float wjv[3];
            float m = 0.f;   // includes the 944 exact-zero logits
#pragma unroll
            for (int t3 = 0; t3 < 3; t3++) {
                int j = lane + 32 * t3;
                float wv = -1e30f;
                if (j < WMAX) {
                    int st = (j > 16) ? (j - 16) : 0;
                    int en = (j + 16 < 64) ? (j + 16) : 64;
                    wv = scs[w][rr][en] - scs[w][rr][st];
                    m = fmaxf(m, wv);
                }
                wjv[t3] = wv;
            }
#pragma unroll
            for (int off = 16; off >= 1; off >>= 1)
                m = fmaxf(m, __shfl_xor_sync(0xffffffffu, m, off));

            float zs = 0.f;
#pragma unroll
            for (int t3 = 0; t3 < 3; t3++) {
                int j = lane + 32 * t3;
                if (j < WMAX) {
                    float e = __expf(wjv[t3] - m);
                    zs += e;
                    wjv[t3] = e;
                }
            }
#pragma unroll
            for (int off = 16; off >= 1; off >>= 1)
                zs += __shfl_xor_sync(0xffffffffu, zs, off);

            const float em   = __expf(-m);
            const float invZ = 1.0f / (zs + 944.0f * em);
#pragma unroll
            for (int t3 = 0; t3 < 3; t3++) {
                int j = lane + 32 * t3;
                if (j < WMAX) wbuf[w][rr][j] = wjv[t3] * invZ;
            }
            cr[rr] = em * invZ;
            __syncwarp();
        }

        float2 acc[4];
#pragma unroll
        for (int rr = 0; rr < 4; rr++)
            acc[rr] = make_float2(cr[rr] * S2.x, cr[rr] * S2.y);
#pragma unroll 4
        for (int j = 0; j < WMAX; j++) {
            const float2 vv = *(const float2*)&Vs[j][lane * 2];
#pragma unroll
            for (int rr = 0; rr < 4; rr++) {
                const float aj = wbuf[w][rr][j];
                acc[rr].x = fmaf(aj, vv.x, acc[rr].x);
                acc[rr].y = fmaf(aj, vv.y, acc[rr].y);
            }
        }
#pragma unroll
        for (int rr = 0; rr < 4; rr++)
            *(float2*)(out + base + (size_t)(ibase + rr) * C_ + lane * 2) = acc[rr];
        __syncwarp();
    }
}

// ---------------------------------------------------------------------------
extern "C" void kernel_launch(void* const* d_in, const int* in_sizes, int n_in,
                              void* d_out, int out_size)
{
    const float* q  = (const float*)d_in[0];
    const float* k  = (const float*)d_in[1];
    const float* v  = (const float*)d_in[2];
    const float* Wq = (const float*)d_in[3];
    const float* Wk = (const float*)d_in[4];
    const float* Wv = (const float*)d_in[5];
    const float* Wp = (const float*)d_in[6];
    const float* bp = (const float*)d_in[7];
    float* out = (float*)d_out;

    float *qp, *kp, *vp, *o1;
    __half *a3, *w3;
    cudaGetSymbolAddress((void**)&qp, g_qp);
    cudaGetSymbolAddress((void**)&kp, g_kp);
    cudaGetSymbolAddress((void**)&vp, g_vp);
    cudaGetSymbolAddress((void**)&o1, g_o1);
    cudaGetSymbolAddress((void**)&a3, g_a3);
    cudaGetSymbolAddress((void**)&w3, g_w3);

    cudaFuncSetAttribute(gemm_f16s, cudaFuncAttributeMaxDynamicSharedMemorySize, GEMM_SMEM);

    const int nA4 = MTOT * C_ / 4;   // 1,048,576
    const int nW4 = C_ * C_ / 4;     // 262,144
    dim3 gg(C_ / 256, MTOT / 128);   // (4, 32) = 128 CTAs
    dim3 ga(T_ / 256, H_, B_);       // (4, 16, 4)

    // Q projection: 2-term fp16 (K=2048)
    splitk_kernel<<<nA4 / 256, 256>>>(q, a3, nA4, -1, 1024);
    splitk_kernel<<<nW4 / 256, 256>>>(Wq, w3, nW4, 1024, -1);
    gemm_f16s<<<gg, 256, GEMM_SMEM>>>(a3, w3, nullptr, qp, 32);
    // K projection: 2-term fp16 (K=2048)
    splitk_kernel<<<nA4 / 256, 256>>>(k, a3, nA4, -1, 1024);
    splitk_kernel<<<nW4 / 256, 256>>>(Wk, w3, nW4, 1024, -1);
    gemm_f16s<<<gg, 256, GEMM_SMEM>>>(a3, w3, nullptr, kp, 32);
    // V projection: 3-term fp16 (K=3072)
    splitk_kernel<<<nA4 / 256, 256>>>(v, a3, nA4, 2048, 1024);
    splitk_kernel<<<nW4 / 256, 256>>>(Wv, w3, nW4, 1024, 2048);
    gemm_f16s<<<gg, 256, GEMM_SMEM>>>(a3, w3, nullptr, vp, 48);

    attn_kernel<<<ga, 256>>>(qp, kp, vp, o1);

    // Output projection (+bias): 3-term fp16 (K=3072)
    splitk_kernel<<<nA4 / 256, 256>>>(o1, a3, nA4, 2048, 1024);
    splitk_kernel<<<nW4 / 256, 256>>>(Wp, w3, nW4, 1024, 2048);
    gemm_f16s<<<gg, 256, GEMM_SMEM>>>(a3, w3, bp, out, 48);
}

// round 5
// speedup vs baseline: 3.7325x; 1.2758x over previous
#include <cuda_runtime.h>
#include <cuda_fp16.h>
#include <cstdint>

// Problem constants
#define B_ 4
#define T_ 1024
#define C_ 1024
#define H_ 16
#define D_ 64
#define WMAX 80           // logits j >= 80 are exactly zero
#define MTOT (B_ * T_)    // 4096
#define KP 3072           // buffer pitch (max split-K)
#define STAGE_BYTES 49152 // A 16KB + B 32KB per stage
#define NSTAGE 4
#define GEMM_SMEM (NSTAGE * STAGE_BYTES)   // 196608

// Scratch (allocation-free rule: __device__ globals)
static __device__ float g_qp[MTOT * C_];
static __device__ float g_kp[MTOT * C_];
static __device__ float g_vp[MTOT * C_];
static __device__ __align__(16) __half g_a3[MTOT * KP];  // 24 MB
static __device__ __align__(16) __half g_w3[C_ * KP];    // 6 MB

// ---------------------------------------------------------------------------
// PTX helpers (plain sm_103-safe)
// ---------------------------------------------------------------------------
__device__ __forceinline__ uint32_t smem_u32(const void* p) {
    uint32_t a;
    asm("{ .reg .u64 t; cvta.to.shared.u64 t, %1; cvt.u32.u64 %0, t; }" : "=r"(a) : "l"(p));
    return a;
}
__device__ __forceinline__ void cp16(uint32_t dst, const void* src) {
    asm volatile("cp.async.cg.shared.global [%0], [%1], 16;" :: "r"(dst), "l"(src));
}
#define CP_COMMIT() asm volatile("cp.async.commit_group;" ::: "memory")
#define CP_WAIT(n)  asm volatile("cp.async.wait_group %0;" :: "n"(n) : "memory")

#define LDSM4(r0, r1, r2, r3, addr) \
    asm volatile("ldmatrix.sync.aligned.m8n8.x4.shared.b16 {%0,%1,%2,%3}, [%4];" \
                 : "=r"(r0), "=r"(r1), "=r"(r2), "=r"(r3) : "r"(addr))

#define MMA_F16(d, a, b0, b1) \
    asm volatile("mma.sync.aligned.m16n8k16.row.col.f32.f16.f16.f32 " \
                 "{%0,%1,%2,%3},{%4,%5,%6,%7},{%8,%9},{%0,%1,%2,%3};" \
                 : "+f"((d)[0]), "+f"((d)[1]), "+f"((d)[2]), "+f"((d)[3]) \
                 : "r"((a)[0]), "r"((a)[1]), "r"((a)[2]), "r"((a)[3]), \
                   "r"(b0), "r"(b1))

__device__ __forceinline__ uint32_t swz(uint32_t off) {   // SW128
    return off ^ ((off >> 3) & 0x70);
}

// ---------------------------------------------------------------------------
// Split fp32 -> fp16 multi-block layout, dst row pitch KP (=3072).
//   hi written at col+0; if dupOff>=0 hi also at col+dupOff;
//   if loOff>=0 lo at col+loOff.
//   1-term:      (dup=-1,   lo=-1)   -> [Xh]
//   act 2-term:  (dup=-1,   lo=1024) -> [Xh, Xl]
//   wgt 2-term:  (dup=1024, lo=-1)   -> [Wh, Wh]
//   wgt 3-term:  (dup=1024, lo=2048) -> [Wh, Wh, Wl]
// ---------------------------------------------------------------------------
__global__ __launch_bounds__(256) void splitk_kernel(
    const float* __restrict__ x, __half* __restrict__ dst,
    int n4, int dupOff, int loOff)
{
    int i = blockIdx.x * 256 + threadIdx.x;
    if (i >= n4) return;
    float4 v = ((const float4*)x)[i];
    __half h0 = __float2half_rn(v.x);
    __half h1 = __float2half_rn(v.y);
    __half h2 = __float2half_rn(v.z);
    __half h3 = __float2half_rn(v.w);
    uint2 ph;
    ph.x = ((uint32_t)__half_as_ushort(h1) << 16) | __half_as_ushort(h0);
    ph.y = ((uint32_t)__half_as_ushort(h3) << 16) | __half_as_ushort(h2);
    int m   = i >> 8;            // 256 float4 per source row (C_=1024)
    int col = (i & 255) * 4;
    size_t base = (size_t)m * KP + col;
    *(uint2*)(dst + base) = ph;
    if (dupOff >= 0) *(uint2*)(dst + base + dupOff) = ph;
    if (loOff >= 0) {
        __half l0 = __float2half_rn(v.x - __half2float(h0));
        __half l1 = __float2half_rn(v.y - __half2float(h1));
        __half l2 = __float2half_rn(v.z - __half2float(h2));
        __half l3 = __float2half_rn(v.w - __half2float(h3));
        uint2 pl;
        pl.x = ((uint32_t)__half_as_ushort(l1) << 16) | __half_as_ushort(l0);
        pl.y = ((uint32_t)__half_as_ushort(l3) << 16) | __half_as_ushort(l2);
        *(uint2*)(dst + base + loOff) = pl;
    }
}

// ---------------------------------------------------------------------------
// fp16 NT GEMM via mma.sync m16n8k16: C[m,n] = sum_k A[m,k]*W[n,k] (+bias)
// M=4096, N=1024, K = KT*64 (runtime). CTA 128x256, 8 warps (2x4),
// warp tile 64x64. SW128 smem, 4-stage cp.async pipeline, K-tile 64.
// Buffers have fixed row pitch KP.
// ---------------------------------------------------------------------------
__global__ __launch_bounds__(256, 1) void gemm_f16s(
    const __half* __restrict__ A3, const __half* __restrict__ W3,
    const float* __restrict__ bias, float* __restrict__ Cout, int KT)
{
    extern __shared__ char smem[];
    const uint32_t sb = smem_u32(smem);
    const int tid  = threadIdx.x;
    const int lane = tid & 31;
    const int wid  = tid >> 5;
    const int bm   = blockIdx.y * 128;
    const int bn   = blockIdx.x * 256;
    const int wm   = (wid >> 2) * 64;   // warp M offset (0/64)
    const int wn   = (wid & 3) * 64;    // warp N offset (0/64/128/192)

    float acc[4][8][4];
#pragma unroll
    for (int i = 0; i < 4; i++)
#pragma unroll
        for (int j = 0; j < 8; j++)
#pragma unroll
            for (int c = 0; c < 4; c++) acc[i][j][c] = 0.f;

    // per-stage: A 128 rows (16 KB) then B 256 rows (32 KB), 128B/row, SW128
    auto issue = [&](int kt) {
        const int stage = kt & (NSTAGE - 1);
        const int k0 = kt * 64;
#pragma unroll
        for (int it = 0; it < 12; it++) {
            int idx = tid + it * 256;          // 0..3071
            int isB = idx >= 1024;
            int l   = isB ? (idx - 1024) : idx;
            int row = l >> 3, ch = l & 7;
            const __half* src =
                (isB ? W3 + (size_t)(bn + row) * KP : A3 + (size_t)(bm + row) * KP)
                + k0 + ch * 8;
            uint32_t off = (uint32_t)row * 128 + ch * 16;
            uint32_t dst = sb + stage * STAGE_BYTES + (isB ? 16384 : 0) + swz(off);
            cp16(dst, src);
        }
    };

    issue(0); CP_COMMIT();
    issue(1); CP_COMMIT();
    issue(2); CP_COMMIT();

    // ldmatrix per-lane address components
    const uint32_t rA = wm + (lane & 7) + ((lane >> 3) & 1) * 8;
    const uint32_t kA = ((lane >> 4) & 1) * 16;                  // bytes
    const uint32_t rB = wn + (lane & 7) + ((lane >> 4) & 1) * 8;
    const uint32_t kB = ((lane >> 3) & 1) * 16;                  // bytes

#pragma unroll 1
    for (int kt = 0; kt < KT; kt++) {
        CP_WAIT(2);
        __syncthreads();
        if (kt + 3 < KT) issue(kt + 3);
        CP_COMMIT();

        const uint32_t sA = sb + (kt & (NSTAGE - 1)) * STAGE_BYTES;
        const uint32_t sB = sA + 16384;
#pragma unroll
        for (int ks = 0; ks < 4; ks++) {
            uint32_t a[4][4], b[4][4];
#pragma unroll
            for (int ti = 0; ti < 4; ti++) {
                uint32_t off = (rA + ti * 16) * 128 + ks * 32 + kA;
                LDSM4(a[ti][0], a[ti][1], a[ti][2], a[ti][3], sA + swz(off));
            }
#pragma unroll
            for (int tp = 0; tp < 4; tp++) {
                uint32_t off = (rB + tp * 16) * 128 + ks * 32 + kB;
                LDSM4(b[tp][0], b[tp][1], b[tp][2], b[tp][3], sB + swz(off));
            }
#pragma unroll
            for (int ti = 0; ti < 4; ti++)
#pragma unroll
                for (int tj = 0; tj < 8; tj++)
                    MMA_F16(acc[ti][tj], a[ti], b[tj >> 1][(tj & 1) * 2],
                            b[tj >> 1][(tj & 1) * 2 + 1]);
        }
    }

    // Epilogue
    const int col0 = bn + wn + (lane & 3) * 2;
    const int r0   = lane >> 2;
#pragma unroll
    for (int ti = 0; ti < 4; ti++) {
        const int row = bm + wm + ti * 16 + r0;
#pragma unroll
        for (int tj = 0; tj < 8; tj++) {
            float2 bv = bias ? *(const float2*)(bias + col0 + tj * 8)
                             : make_float2(0.f, 0.f);
            float2 v0 = make_float2(acc[ti][tj][0] + bv.x, acc[ti][tj][1] + bv.y);
            float2 v1 = make_float2(acc[ti][tj][2] + bv.x, acc[ti][tj][3] + bv.y);
            *(float2*)(Cout + (size_t)row * C_ + col0 + tj * 8)       = v0;
            *(float2*)(Cout + (size_t)(row + 8) * C_ + col0 + tj * 8) = v1;
        }
    }
}

// ---------------------------------------------------------------------------
// Attention: logits nonzero only for j<80; 944 tail logits are exactly 0.
// out[i] = sum_{j<80} a_j * V[j] + (e^{-m}/Z) * sum_{j>=80} V[j]
// 1 warp = 32 rows processed as 8 quads of 4.
// Epilogue writes the fp16 3-term split [Oh, Ol, Oh] directly into the GEMM
// A-buffer (pitch KP) — no fp32 o1 round-trip, no separate split kernel.
// ---------------------------------------------------------------------------
__global__ __launch_bounds__(256) void attn_kernel(
    const float* __restrict__ qp, const float* __restrict__ kp,
    const float* __restrict__ vp, __half* __restrict__ o3)
{
    __shared__ float Vs[WMAX][D_];       // 20 KB
    __shared__ float Spart[4][D_];
    __shared__ float Ssum[D_];
    __shared__ float wbuf[8][4][WMAX];   // 10 KB
    __shared__ float scs[8][4][68];      // 8.5 KB

    const int tid   = threadIdx.x;
    const int lane  = tid & 31;
    const int w     = tid >> 5;
    const int chunk = blockIdx.x;        // 0..3
    const int h     = blockIdx.y;
    const int b     = blockIdx.z;
    const size_t base = (size_t)b * T_ * C_ + (size_t)h * D_;

    for (int idx = tid; idx < WMAX * D_; idx += 256) {
        int j = idx >> 6, d = idx & 63;
        Vs[j][d] = vp[base + (size_t)j * C_ + d];
    }
    {
        int d = tid & 63, part = tid >> 6;
        float s = 0.f;
        for (int j = WMAX + part; j < T_; j += 4)
            s += vp[base + (size_t)j * C_ + d];
        Spart[part][d] = s;
    }
    __syncthreads();
    if (tid < D_)
        Ssum[tid] = Spart[0][tid] + Spart[1][tid] + Spart[2][tid] + Spart[3][tid];
    __syncthreads();

    const float2 S2 = *(const float2*)&Ssum[lane * 2];

    for (int rq = 0; rq < 8; rq++) {
        const int ibase = chunk * 256 + w * 32 + rq * 4;
        float cr[4];
#pragma unroll
        for (int rr = 0; rr < 4; rr++) {
            const int i = ibase + rr;
            const float2 qv = *(const float2*)(qp + base + (size_t)i * C_ + lane * 2);
            const float2 kv = *(const float2*)(kp + base + (size_t)i * C_ + lane * 2);
            const float p0 = qv.x * kv.x * 0.125f;
            const float p1 = qv.y * kv.y * 0.125f;

            float s = p0 + p1;
#pragma unroll
            for (int off = 1; off < 32; off <<= 1) {
                float t = __shfl_up_sync(0xffffffffu, s, off);
                if (lane >= off) s += t;
            }
            scs[w][rr][2 * lane + 1] = s - p1;
            scs[w][rr][2 * lane + 2] = s;
            if (lane == 0) scs[w][rr][0] = 0.f;
            __syncwarp();

            float wjv[3];
            float m = 0.f;   // includes the 944 exact-zero logits
#pragma unroll
            for (int t3 = 0; t3 < 3; t3++) {
                int j = lane + 32 * t3;
                float wv = -1e30f;
                if (j < WMAX) {
                    int st = (j > 16) ? (j - 16) : 0;
                    int en = (j + 16 < 64) ? (j + 16) : 64;
                    wv = scs[w][rr][en] - scs[w][rr][st];
                    m = fmaxf(m, wv);
                }
                wjv[t3] = wv;
            }
#pragma unroll
            for (int off = 16; off >= 1; off >>= 1)
                m = fmaxf(m, __shfl_xor_sync(0xffffffffu, m, off));

            float zs = 0.f;
#pragma unroll
            for (int t3 = 0; t3 < 3; t3++) {
                int j = lane + 32 * t3;
                if (j < WMAX) {
                    float e = __expf(wjv[t3] - m);
                    zs += e;
                    wjv[t3] = e;
                }
            }
#pragma unroll
            for (int off = 16; off >= 1; off >>= 1)
                zs += __shfl_xor_sync(0xffffffffu, zs, off);

            const float em   = __expf(-m);
            const float invZ = 1.0f / (zs + 944.0f * em);
#pragma unroll
            for (int t3 = 0; t3 < 3; t3++) {
                int j = lane + 32 * t3;
                if (j < WMAX) wbuf[w][rr][j] = wjv[t3] * invZ;
            }
            cr[rr] = em * invZ;
            __syncwarp();
        }

        float2 acc[4];
#pragma unroll
        for (int rr = 0; rr < 4; rr++)
            acc[rr] = make_float2(cr[rr] * S2.x, cr[rr] * S2.y);
#pragma unroll 4
        for (int j = 0; j < WMAX; j++) {
            const float2 vv = *(const float2*)&Vs[j][lane * 2];
#pragma unroll
            for (int rr = 0; rr < 4; rr++) {
                const float aj = wbuf[w][rr][j];
                acc[rr].x = fmaf(aj, vv.x, acc[rr].x);
                acc[rr].y = fmaf(aj, vv.y, acc[rr].y);
            }
        }
#pragma unroll
        for (int rr = 0; rr < 4; rr++) {
            const __half h0 = __float2half_rn(acc[rr].x);
            const __half h1 = __float2half_rn(acc[rr].y);
            const __half l0 = __float2half_rn(acc[rr].x - __half2float(h0));
            const __half l1 = __float2half_rn(acc[rr].y - __half2float(h1));
            const __half2 hh = __halves2half2(h0, h1);
            const size_t rb = (size_t)(b * T_ + ibase + rr) * KP + h * D_ + lane * 2;
            *(__half2*)(o3 + rb)        = hh;
            *(__half2*)(o3 + rb + 1024) = __halves2half2(l0, l1);
            *(__half2*)(o3 + rb + 2048) = hh;
        }
        __syncwarp();
    }
}

// ---------------------------------------------------------------------------
extern "C" void kernel_launch(void* const* d_in, const int* in_sizes, int n_in,
                              void* d_out, int out_size)
{
    const float* q  = (const float*)d_in[0];
    const float* k  = (const float*)d_in[1];
    const float* v  = (const float*)d_in[2];
    const float* Wq = (const float*)d_in[3];
    const float* Wk = (const float*)d_in[4];
    const float* Wv = (const float*)d_in[5];
    const float* Wp = (const float*)d_in[6];
    const float* bp = (const float*)d_in[7];
    float* out = (float*)d_out;

    float *qp, *kp, *vp;
    __half *a3, *w3;
    cudaGetSymbolAddress((void**)&qp, g_qp);
    cudaGetSymbolAddress((void**)&kp, g_kp);
    cudaGetSymbolAddress((void**)&vp, g_vp);
    cudaGetSymbolAddress((void**)&a3, g_a3);
    cudaGetSymbolAddress((void**)&w3, g_w3);

    cudaFuncSetAttribute(gemm_f16s, cudaFuncAttributeMaxDynamicSharedMemorySize, GEMM_SMEM);

    const int nA4 = MTOT * C_ / 4;   // 1,048,576
    const int nW4 = C_ * C_ / 4;     // 262,144
    dim3 gg(C_ / 256, MTOT / 128);   // (4, 32) = 128 CTAs
    dim3 ga(T_ / 256, H_, B_);       // (4, 16, 4)

    // Q projection: 1-term fp16 (K=1024) — error damped by softmax
    splitk_kernel<<<nA4 / 256, 256>>>(q, a3, nA4, -1, -1);
    splitk_kernel<<<nW4 / 256, 256>>>(Wq, w3, nW4, -1, -1);
    gemm_f16s<<<gg, 256, GEMM_SMEM>>>(a3, w3, nullptr, qp, 16);
    // K projection: 1-term fp16 (K=1024)
    splitk_kernel<<<nA4 / 256, 256>>>(k, a3, nA4, -1, -1);
    splitk_kernel<<<nW4 / 256, 256>>>(Wk, w3, nW4, -1, -1);
    gemm_f16s<<<gg, 256, GEMM_SMEM>>>(a3, w3, nullptr, kp, 16);
    // V projection: 2-term fp16 (K=2048)
    splitk_kernel<<<nA4 / 256, 256>>>(v, a3, nA4, -1, 1024);
    splitk_kernel<<<nW4 / 256, 256>>>(Wv, w3, nW4, 1024, -1);
    gemm_f16s<<<gg, 256, GEMM_SMEM>>>(a3, w3, nullptr, vp, 32);

    // Attention writes split o1 [Oh, Ol, Oh] directly into a3
    attn_kernel<<<ga, 256>>>(qp, kp, vp, a3);

    // Output projection (+bias): 3-term fp16 (K=3072)
    splitk_kernel<<<nW4 / 256, 256>>>(Wp, w3, nW4, 1024, 2048);
    gemm_f16s<<<gg, 256, GEMM_SMEM>>>(a3, w3, bp, out, 48);
}

// round 6
// speedup vs baseline: 4.2063x; 1.1269x over previous
#include <cuda_runtime.h>
#include <cuda_fp16.h>
#include <cstdint>

// Problem constants
#define B_ 4
#define T_ 1024
#define C_ 1024
#define H_ 16
#define D_ 64
#define WMAX 80           // logits j >= 80 are exactly zero
#define MTOT (B_ * T_)    // 4096
#define STAGE_BYTES 49152 // A 16KB + B 32KB per stage
#define NSTAGE 4
#define GEMM_SMEM (NSTAGE * STAGE_BYTES)   // 196608

// Scratch (allocation-free rule: __device__ globals)
static __device__ float g_qp[MTOT * C_];
static __device__ float g_kp[MTOT * C_];
static __device__ float g_vp[MTOT * C_];
static __device__ float g_S[B_ * H_ * D_];
static __device__ __align__(16) __half g_aq[MTOT * 1024];  // 8 MB
static __device__ __align__(16) __half g_ak[MTOT * 1024];  // 8 MB
static __device__ __align__(16) __half g_av[MTOT * 2048];  // 16 MB
static __device__ __align__(16) __half g_ap[MTOT * 2048];  // 16 MB
static __device__ __align__(16) __half g_wq[C_ * 1024];    // 2 MB
static __device__ __align__(16) __half g_wk[C_ * 1024];    // 2 MB
static __device__ __align__(16) __half g_wv[C_ * 2048];    // 4 MB
static __device__ __align__(16) __half g_wp[C_ * 2048];    // 4 MB

// ---------------------------------------------------------------------------
// PTX helpers (plain sm_103-safe)
// ---------------------------------------------------------------------------
__device__ __forceinline__ uint32_t smem_u32(const void* p) {
    uint32_t a;
    asm("{ .reg .u64 t; cvta.to.shared.u64 t, %1; cvt.u32.u64 %0, t; }" : "=r"(a) : "l"(p));
    return a;
}
__device__ __forceinline__ void cp16(uint32_t dst, const void* src) {
    asm volatile("cp.async.cg.shared.global [%0], [%1], 16;" :: "r"(dst), "l"(src));
}
#define CP_COMMIT() asm volatile("cp.async.commit_group;" ::: "memory")
#define CP_WAIT(n)  asm volatile("cp.async.wait_group %0;" :: "n"(n) : "memory")

#define LDSM4(r0, r1, r2, r3, addr) \
    asm volatile("ldmatrix.sync.aligned.m8n8.x4.shared.b16 {%0,%1,%2,%3}, [%4];" \
                 : "=r"(r0), "=r"(r1), "=r"(r2), "=r"(r3) : "r"(addr))

#define MMA_F16(d, a, b0, b1) \
    asm volatile("mma.sync.aligned.m16n8k16.row.col.f32.f16.f16.f32 " \
                 "{%0,%1,%2,%3},{%4,%5,%6,%7},{%8,%9},{%0,%1,%2,%3};" \
                 : "+f"((d)[0]), "+f"((d)[1]), "+f"((d)[2]), "+f"((d)[3]) \
                 : "r"((a)[0]), "r"((a)[1]), "r"((a)[2]), "r"((a)[3]), \
                   "r"(b0), "r"(b1))

__device__ __forceinline__ uint32_t swz(uint32_t off) {   // SW128
    return off ^ ((off >> 3) & 0x70);
}

// ---------------------------------------------------------------------------
// Unified split: all 7 conversion jobs in one launch (blockIdx.y = job).
// Source rows are always C_=1024 floats. dst row pitch per job.
//   hi at col+0; if dupOff>=0 hi also at col+dupOff; if loOff>=0 lo at col+loOff
// ---------------------------------------------------------------------------
struct SplitJobs {
    const float* src[7];
    __half*      dst[7];
    int          n4[7];
    int          pitch[7];
    int          dupOff[7];
    int          loOff[7];
};

__global__ __launch_bounds__(256) void split_all_kernel(SplitJobs J)
{
    const int j = blockIdx.y;
    int i = blockIdx.x * 256 + threadIdx.x;
    if (i >= J.n4[j]) return;
    float4 v = ((const float4*)J.src[j])[i];
    __half h0 = __float2half_rn(v.x);
    __half h1 = __float2half_rn(v.y);
    __half h2 = __float2half_rn(v.z);
    __half h3 = __float2half_rn(v.w);
    uint2 ph;
    ph.x = ((uint32_t)__half_as_ushort(h1) << 16) | __half_as_ushort(h0);
    ph.y = ((uint32_t)__half_as_ushort(h3) << 16) | __half_as_ushort(h2);
    int m   = i >> 8;            // 256 float4 per source row
    int col = (i & 255) * 4;
    __half* dst = J.dst[j];
    size_t base = (size_t)m * J.pitch[j] + col;
    *(uint2*)(dst + base) = ph;
    if (J.dupOff[j] >= 0) *(uint2*)(dst + base + J.dupOff[j]) = ph;
    if (J.loOff[j] >= 0) {
        __half l0 = __float2half_rn(v.x - __half2float(h0));
        __half l1 = __float2half_rn(v.y - __half2float(h1));
        __half l2 = __float2half_rn(v.z - __half2float(h2));
        __half l3 = __float2half_rn(v.w - __half2float(h3));
        uint2 pl;
        pl.x = ((uint32_t)__half_as_ushort(l1) << 16) | __half_as_ushort(l0);
        pl.y = ((uint32_t)__half_as_ushort(l3) << 16) | __half_as_ushort(l2);
        *(uint2*)(dst + base + J.loOff[j]) = pl;
    }
}

// ---------------------------------------------------------------------------
// fp16 NT GEMM via mma.sync m16n8k16: C[m,n] = sum_k A[m,k]*W[n,k] (+bias)
// M=4096, N=1024, K = KT*64. CTA 128x256, 8 warps (2x4), warp tile 64x64.
// SW128 smem, 4-stage cp.async pipeline. blockIdx.z selects job (QK fusion).
// ---------------------------------------------------------------------------
struct GemmJob {
    const __half* A;
    const __half* W;
    const float*  bias;
    float*        C;
};

__global__ __launch_bounds__(256, 1) void gemm_f16s(
    GemmJob j0, GemmJob j1, int KT, int pitch)
{
    extern __shared__ char smem[];
    const GemmJob& J = blockIdx.z ? j1 : j0;
    const __half* __restrict__ A3 = J.A;
    const __half* __restrict__ W3 = J.W;
    const uint32_t sb = smem_u32(smem);
    const int tid  = threadIdx.x;
    const int lane = tid & 31;
    const int wid  = tid >> 5;
    const int bm   = blockIdx.y * 128;
    const int bn   = blockIdx.x * 256;
    const int wm   = (wid >> 2) * 64;
    const int wn   = (wid & 3) * 64;

    float acc[4][8][4];
#pragma unroll
    for (int i = 0; i < 4; i++)
#pragma unroll
        for (int j = 0; j < 8; j++)
#pragma unroll
            for (int c = 0; c < 4; c++) acc[i][j][c] = 0.f;

    auto issue = [&](int kt) {
        const int stage = kt & (NSTAGE - 1);
        const int k0 = kt * 64;
#pragma unroll
        for (int it = 0; it < 12; it++) {
            int idx = tid + it * 256;          // 0..3071
            int isB = idx >= 1024;
            int l   = isB ? (idx - 1024) : idx;
            int row = l >> 3, ch = l & 7;
            const __half* src =
                (isB ? W3 + (size_t)(bn + row) * pitch : A3 + (size_t)(bm + row) * pitch)
                + k0 + ch * 8;
            uint32_t off = (uint32_t)row * 128 + ch * 16;
            uint32_t dst = sb + stage * STAGE_BYTES + (isB ? 16384 : 0) + swz(off);
            cp16(dst, src);
        }
    };

    issue(0); CP_COMMIT();
    issue(1); CP_COMMIT();
    issue(2); CP_COMMIT();

    const uint32_t rA = wm + (lane & 7) + ((lane >> 3) & 1) * 8;
    const uint32_t kA = ((lane >> 4) & 1) * 16;
    const uint32_t rB = wn + (lane & 7) + ((lane >> 4) & 1) * 8;
    const uint32_t kB = ((lane >> 3) & 1) * 16;

#pragma unroll 1
    for (int kt = 0; kt < KT; kt++) {
        CP_WAIT(2);
        __syncthreads();
        if (kt + 3 < KT) issue(kt + 3);
        CP_COMMIT();

        const uint32_t sA = sb + (kt & (NSTAGE - 1)) * STAGE_BYTES;
        const uint32_t sB = sA + 16384;
#pragma unroll
        for (int ks = 0; ks < 4; ks++) {
            uint32_t a[4][4], b[4][4];
#pragma unroll
            for (int ti = 0; ti < 4; ti++) {
                uint32_t off = (rA + ti * 16) * 128 + ks * 32 + kA;
                LDSM4(a[ti][0], a[ti][1], a[ti][2], a[ti][3], sA + swz(off));
            }
#pragma unroll
            for (int tp = 0; tp < 4; tp++) {
                uint32_t off = (rB + tp * 16) * 128 + ks * 32 + kB;
                LDSM4(b[tp][0], b[tp][1], b[tp][2], b[tp][3], sB + swz(off));
            }
#pragma unroll
            for (int ti = 0; ti < 4; ti++)
#pragma unroll
                for (int tj = 0; tj < 8; tj++)
                    MMA_F16(acc[ti][tj], a[ti], b[tj >> 1][(tj & 1) * 2],
                            b[tj >> 1][(tj & 1) * 2 + 1]);
        }
    }

    // Epilogue
    float* __restrict__ Cout = J.C;
    const float* bias = J.bias;
    const int col0 = bn + wn + (lane & 3) * 2;
    const int r0   = lane >> 2;
#pragma unroll
    for (int ti = 0; ti < 4; ti++) {
        const int row = bm + wm + ti * 16 + r0;
#pragma unroll
        for (int tj = 0; tj < 8; tj++) {
            float2 bv = bias ? *(const float2*)(bias + col0 + tj * 8)
                             : make_float2(0.f, 0.f);
            float2 v0 = make_float2(acc[ti][tj][0] + bv.x, acc[ti][tj][1] + bv.y);
            float2 v1 = make_float2(acc[ti][tj][2] + bv.x, acc[ti][tj][3] + bv.y);
            *(float2*)(Cout + (size_t)row * C_ + col0 + tj * 8)       = v0;
            *(float2*)(Cout + (size_t)(row + 8) * C_ + col0 + tj * 8) = v1;
        }
    }
}

// ---------------------------------------------------------------------------
// Tail V sum: S[b,h,d] = sum_{j=80..1023} vp[b,j,h*64+d]. One block per (b,h).
// ---------------------------------------------------------------------------
__global__ __launch_bounds__(256) void sum_tail_kernel(
    const float* __restrict__ vp, float* __restrict__ S)
{
    __shared__ float part[4][D_];
    const int bh = blockIdx.x;           // 0..63
    const int b  = bh >> 4, h = bh & 15;
    const int tid = threadIdx.x;
    const int d = tid & 63, p = tid >> 6;
    const size_t base = (size_t)b * T_ * C_ + (size_t)h * D_;
    float s = 0.f;
    for (int j = WMAX + p; j < T_; j += 4)
        s += vp[base + (size_t)j * C_ + d];
    part[p][d] = s;
    __syncthreads();
    if (tid < D_)
        S[bh * D_ + tid] = part[0][tid] + part[1][tid] + part[2][tid] + part[3][tid];
}

// ---------------------------------------------------------------------------
// Attention: logits nonzero only for j<80; 944 tail logits are exactly 0.
// out[i] = sum_{j<80} a_j * V[j] + (e^{-m}/Z) * S[b,h]
// Block = 128 rows (grid 8x16x4 = 512 CTAs). 1 warp = 16 rows (4 quads).
// Epilogue writes the fp16 2-term split [Oh, Ol] into the P GEMM A-buffer
// (pitch 2048) — no fp32 o1 round-trip.
// ---------------------------------------------------------------------------
__global__ __launch_bounds__(256) void attn_kernel(
    const float* __restrict__ qp, const float* __restrict__ kp,
    const float* __restrict__ vp, const float* __restrict__ gS,
    __half* __restrict__ o2)
{
    __shared__ float Vs[WMAX][D_];       // 20 KB
    __shared__ float wbuf[8][4][WMAX];   // 10 KB
    __shared__ float scs[8][4][68];      // 8.5 KB

    const int tid   = threadIdx.x;
    const int lane  = tid & 31;
    const int w     = tid >> 5;
    const int chunk = blockIdx.x;        // 0..7
    const int h     = blockIdx.y;
    const int b     = blockIdx.z;
    const size_t base = (size_t)b * T_ * C_ + (size_t)h * D_;

    for (int idx = tid; idx < WMAX * D_; idx += 256) {
        int j = idx >> 6, d = idx & 63;
        Vs[j][d] = vp[base + (size_t)j * C_ + d];
    }
    __syncthreads();

    const float2 S2 = *(const float2*)(gS + (b * H_ + h) * D_ + lane * 2);

    for (int rq = 0; rq < 4; rq++) {
        const int ibase = chunk * 128 + w * 16 + rq * 4;
        float cr[4];
#pragma unroll
        for (int rr = 0; rr < 4; rr++) {
            const int i = ibase + rr;
            const float2 qv = *(const float2*)(qp + base + (size_t)i * C_ + lane * 2);
            const float2 kv = *(const float2*)(kp + base + (size_t)i * C_ + lane * 2);
            const float p0 = qv.x * kv.x * 0.125f;
            const float p1 = qv.y * kv.y * 0.125f;

            float s = p0 + p1;
#pragma unroll
            for (int off = 1; off < 32; off <<= 1) {
                float t = __shfl_up_sync(0xffffffffu, s, off);
                if (lane >= off) s += t;
            }
            scs[w][rr][2 * lane + 1] = s - p1;
            scs[w][rr][2 * lane + 2] = s;
            if (lane == 0) scs[w][rr][0] = 0.f;
            __syncwarp();

            float wjv[3];
            float m = 0.f;   // includes the 944 exact-zero logits
#pragma unroll
            for (int t3 = 0; t3 < 3; t3++) {
                int j = lane + 32 * t3;
                float wv = -1e30f;
                if (j < WMAX) {
                    int st = (j > 16) ? (j - 16) : 0;
                    int en = (j + 16 < 64) ? (j + 16) : 64;
                    wv = scs[w][rr][en] - scs[w][rr][st];
                    m = fmaxf(m, wv);
                }
                wjv[t3] = wv;
            }
#pragma unroll
            for (int off = 16; off >= 1; off >>= 1)
                m = fmaxf(m, __shfl_xor_sync(0xffffffffu, m, off));

            float zs = 0.f;
#pragma unroll
            for (int t3 = 0; t3 < 3; t3++) {
                int j = lane + 32 * t3;
                if (j < WMAX) {
                    float e = __expf(wjv[t3] - m);
                    zs += e;
                    wjv[t3] = e;
                }
            }
#pragma unroll
            for (int off = 16; off >= 1; off >>= 1)
                zs += __shfl_xor_sync(0xffffffffu, zs, off);

            const float em   = __expf(-m);
            const float invZ = 1.0f / (zs + 944.0f * em);
#pragma unroll
            for (int t3 = 0; t3 < 3; t3++) {
                int j = lane + 32 * t3;
                if (j < WMAX) wbuf[w][rr][j] = wjv[t3] * invZ;
            }
            cr[rr] = em * invZ;
            __syncwarp();
        }

        float2 acc[4];
#pragma unroll
        for (int rr = 0; rr < 4; rr++)
            acc[rr] = make_float2(cr[rr] * S2.x, cr[rr] * S2.y);
#pragma unroll 4
        for (int j = 0; j < WMAX; j++) {
            const float2 vv = *(const float2*)&Vs[j][lane * 2];
#pragma unroll
            for (int rr = 0; rr < 4; rr++) {
                const float aj = wbuf[w][rr][j];
                acc[rr].x = fmaf(aj, vv.x, acc[rr].x);
                acc[rr].y = fmaf(aj, vv.y, acc[rr].y);
            }
        }
#pragma unroll
        for (int rr = 0; rr < 4; rr++) {
            const __half h0 = __float2half_rn(acc[rr].x);
            const __half h1 = __float2half_rn(acc[rr].y);
            const __half l0 = __float2half_rn(acc[rr].x - __half2float(h0));
            const __half l1 = __float2half_rn(acc[rr].y - __half2float(h1));
            const size_t rb = (size_t)(b * T_ + ibase + rr) * 2048 + h * D_ + lane * 2;
            *(__half2*)(o2 + rb)        = __halves2half2(h0, h1);
            *(__half2*)(o2 + rb + 1024) = __halves2half2(l0, l1);
        }
        __syncwarp();
    }
}

// ---------------------------------------------------------------------------
extern "C" void kernel_launch(void* const* d_in, const int* in_sizes, int n_in,
                              void* d_out, int out_size)
{
    const float* q  = (const float*)d_in[0];
    const float* k  = (const float*)d_in[1];
    const float* v  = (const float*)d_in[2];
    const float* Wq = (const float*)d_in[3];
    const float* Wk = (const float*)d_in[4];
    const float* Wv = (const float*)d_in[5];
    const float* Wp = (const float*)d_in[6];
    const float* bp = (const float*)d_in[7];
    float* out = (float*)d_out;

    float *qp, *kp, *vp, *gS;
    __half *aq, *ak, *av, *ap, *wq, *wk, *wv, *wp;
    cudaGetSymbolAddress((void**)&qp, g_qp);
    cudaGetSymbolAddress((void**)&kp, g_kp);
    cudaGetSymbolAddress((void**)&vp, g_vp);
    cudaGetSymbolAddress((void**)&gS, g_S);
    cudaGetSymbolAddress((void**)&aq, g_aq);
    cudaGetSymbolAddress((void**)&ak, g_ak);
    cudaGetSymbolAddress((void**)&av, g_av);
    cudaGetSymbolAddress((void**)&ap, g_ap);
    cudaGetSymbolAddress((void**)&wq, g_wq);
    cudaGetSymbolAddress((void**)&wk, g_wk);
    cudaGetSymbolAddress((void**)&wv, g_wv);
    cudaGetSymbolAddress((void**)&wp, g_wp);

    cudaFuncSetAttribute(gemm_f16s, cudaFuncAttributeMaxDynamicSharedMemorySize, GEMM_SMEM);

    const int nA4 = MTOT * C_ / 4;   // 1,048,576
    const int nW4 = C_ * C_ / 4;     // 262,144

    // All 7 splits in one launch:
    //  0: q  -> aq  1-term (pitch 1024)
    //  1: k  -> ak  1-term
    //  2: v  -> av  2-term act  [Vh, Vl]   (pitch 2048)
    //  3: Wq -> wq  1-term
    //  4: Wk -> wk  1-term
    //  5: Wv -> wv  2-term wgt  [Wh, Wh]
    //  6: Wp -> wp  2-term wgt  [Wh, Wh]
    SplitJobs J;
    J.src[0] = q;  J.dst[0] = aq; J.n4[0] = nA4; J.pitch[0] = 1024; J.dupOff[0] = -1;   J.loOff[0] = -1;
    J.src[1] = k;  J.dst[1] = ak; J.n4[1] = nA4; J.pitch[1] = 1024; J.dupOff[1] = -1;   J.loOff[1] = -1;
    J.src[2] = v;  J.dst[2] = av; J.n4[2] = nA4; J.pitch[2] = 2048; J.dupOff[2] = -1;   J.loOff[2] = 1024;
    J.src[3] = Wq; J.dst[3] = wq; J.n4[3] = nW4; J.pitch[3] = 1024; J.dupOff[3] = -1;   J.loOff[3] = -1;
    J.src[4] = Wk; J.dst[4] = wk; J.n4[4] = nW4; J.pitch[4] = 1024; J.dupOff[4] = -1;   J.loOff[4] = -1;
    J.src[5] = Wv; J.dst[5] = wv; J.n4[5] = nW4; J.pitch[5] = 2048; J.dupOff[5] = 1024; J.loOff[5] = -1;
    J.src[6] = Wp; J.dst[6] = wp; J.n4[6] = nW4; J.pitch[6] = 2048; J.dupOff[6] = 1024; J.loOff[6] = -1;
    split_all_kernel<<<dim3(nA4 / 256, 7), 256>>>(J);

    dim3 gqk(C_ / 256, MTOT / 128, 2);   // Q and K projections fused
    GemmJob jq = {aq, wq, nullptr, qp};
    GemmJob jk = {ak, wk, nullptr, kp};
    gemm_f16s<<<gqk, 256, GEMM_SMEM>>>(jq, jk, 16, 1024);

    dim3 g1(C_ / 256, MTOT / 128, 1);
    GemmJob jv = {av, wv, nullptr, vp};
    gemm_f16s<<<g1, 256, GEMM_SMEM>>>(jv, jv, 32, 2048);

    sum_tail_kernel<<<B_ * H_, 256>>>(vp, gS);

    dim3 ga(T_ / 128, H_, B_);           // 512 CTAs
    attn_kernel<<<ga, 256>>>(qp, kp, vp, gS, ap);

    GemmJob jp = {ap, wp, bp, out};
    gemm_f16s<<<g1, 256, GEMM_SMEM>>>(jp, jp, 32, 2048);
}

// round 7
// speedup vs baseline: 4.3036x; 1.0231x over previous
#include <cuda_runtime.h>
#include <cuda_fp16.h>
#include <cstdint>

// Problem constants
#define B_ 4
#define T_ 1024
#define C_ 1024
#define H_ 16
#define D_ 64
#define WMAX 80           // logits j >= 80 are exactly zero
#define MTOT (B_ * T_)    // 4096
#define STAGE_BYTES 49152 // A 16KB + B 32KB per stage
#define NSTAGE 4
#define GEMM_SMEM (NSTAGE * STAGE_BYTES)   // 196608
#define NTAILP 8          // tail-sum partials per (b,h)

// Scratch (allocation-free rule: __device__ globals)
static __device__ float g_qp[MTOT * C_];
static __device__ float g_kp[MTOT * C_];
static __device__ float g_vp[MTOT * C_];
static __device__ float g_Sp[B_ * H_ * NTAILP * D_];
static __device__ __align__(16) __half g_aq[MTOT * 1024];  // 8 MB
static __device__ __align__(16) __half g_ak[MTOT * 1024];  // 8 MB
static __device__ __align__(16) __half g_av[MTOT * 2048];  // 16 MB
static __device__ __align__(16) __half g_ap[MTOT * 2048];  // 16 MB
static __device__ __align__(16) __half g_wq[C_ * 1024];    // 2 MB
static __device__ __align__(16) __half g_wk[C_ * 1024];    // 2 MB
static __device__ __align__(16) __half g_wv[C_ * 1024];    // 2 MB
static __device__ __align__(16) __half g_wp[C_ * 1024];    // 2 MB

// ---------------------------------------------------------------------------
// PTX helpers (plain sm_103-safe)
// ---------------------------------------------------------------------------
__device__ __forceinline__ uint32_t smem_u32(const void* p) {
    uint32_t a;
    asm("{ .reg .u64 t; cvta.to.shared.u64 t, %1; cvt.u32.u64 %0, t; }" : "=r"(a) : "l"(p));
    return a;
}
__device__ __forceinline__ void cp16(uint32_t dst, const void* src) {
    asm volatile("cp.async.cg.shared.global [%0], [%1], 16;" :: "r"(dst), "l"(src));
}
#define CP_COMMIT() asm volatile("cp.async.commit_group;" ::: "memory")
#define CP_WAIT(n)  asm volatile("cp.async.wait_group %0;" :: "n"(n) : "memory")

#define LDSM4(r0, r1, r2, r3, addr) \
    asm volatile("ldmatrix.sync.aligned.m8n8.x4.shared.b16 {%0,%1,%2,%3}, [%4];" \
                 : "=r"(r0), "=r"(r1), "=r"(r2), "=r"(r3) : "r"(addr))

#define MMA_F16(d, a, b0, b1) \
    asm volatile("mma.sync.aligned.m16n8k16.row.col.f32.f16.f16.f32 " \
                 "{%0,%1,%2,%3},{%4,%5,%6,%7},{%8,%9},{%0,%1,%2,%3};" \
                 : "+f"((d)[0]), "+f"((d)[1]), "+f"((d)[2]), "+f"((d)[3]) \
                 : "r"((a)[0]), "r"((a)[1]), "r"((a)[2]), "r"((a)[3]), \
                   "r"(b0), "r"(b1))

__device__ __forceinline__ uint32_t swz(uint32_t off) {   // SW128
    return off ^ ((off >> 3) & 0x70);
}

// ---------------------------------------------------------------------------
// Unified split: 7 conversion jobs in one launch (blockIdx.y = job).
// ---------------------------------------------------------------------------
struct SplitJobs {
    const float* src[7];
    __half*      dst[7];
    int          n4[7];
    int          pitch[7];
    int          loOff[7];   // -1: hi only; else lo at col+loOff
};

__global__ __launch_bounds__(256) void split_all_kernel(SplitJobs J)
{
    const int j = blockIdx.y;
    int i = blockIdx.x * 256 + threadIdx.x;
    if (i >= J.n4[j]) return;
    float4 v = ((const float4*)J.src[j])[i];
    __half h0 = __float2half_rn(v.x);
    __half h1 = __float2half_rn(v.y);
    __half h2 = __float2half_rn(v.z);
    __half h3 = __float2half_rn(v.w);
    uint2 ph;
    ph.x = ((uint32_t)__half_as_ushort(h1) << 16) | __half_as_ushort(h0);
    ph.y = ((uint32_t)__half_as_ushort(h3) << 16) | __half_as_ushort(h2);
    int m   = i >> 8;            // 256 float4 per source row
    int col = (i & 255) * 4;
    __half* dst = J.dst[j];
    size_t base = (size_t)m * J.pitch[j] + col;
    *(uint2*)(dst + base) = ph;
    if (J.loOff[j] >= 0) {
        __half l0 = __float2half_rn(v.x - __half2float(h0));
        __half l1 = __float2half_rn(v.y - __half2float(h1));
        __half l2 = __float2half_rn(v.z - __half2float(h2));
        __half l3 = __float2half_rn(v.w - __half2float(h3));
        uint2 pl;
        pl.x = ((uint32_t)__half_as_ushort(l1) << 16) | __half_as_ushort(l0);
        pl.y = ((uint32_t)__half_as_ushort(l3) << 16) | __half_as_ushort(l2);
        *(uint2*)(dst + base + J.loOff[j]) = pl;
    }
}

// ---------------------------------------------------------------------------
// fp16 NT GEMM via mma.sync m16n8k16: C[m,n] = sum_k A[m,k]*W[n,k] (+bias)
// M=4096, N=1024. CTA 128x256, 8 warps (2x4), warp tile 64x64.
// SW128 smem, 4-stage cp.async pipeline. blockIdx.z selects the job.
// A row pitch per job; W is always 1024 wide — the B K-index wraps at 16
// tiles so split-lo passes re-read the same hi weights (L2-resident).
// ---------------------------------------------------------------------------
struct GemmJobs {
    const __half* A[3];
    const __half* W[3];
    const float*  bias[3];
    float*        C[3];
    int           KT[3];
    int           pitchA[3];
};

__global__ __launch_bounds__(256, 1) void gemm_f16s(GemmJobs Js)
{
    extern __shared__ char smem[];
    const int z = blockIdx.z;
    const __half* __restrict__ A3 = Js.A[z];
    const __half* __restrict__ W3 = Js.W[z];
    const int KT     = Js.KT[z];
    const int pitchA = Js.pitchA[z];
    const uint32_t sb = smem_u32(smem);
    const int tid  = threadIdx.x;
    const int lane = tid & 31;
    const int wid  = tid >> 5;
    const int bm   = blockIdx.y * 128;
    const int bn   = blockIdx.x * 256;
    const int wm   = (wid >> 2) * 64;
    const int wn   = (wid & 3) * 64;

    float acc[4][8][4];
#pragma unroll
    for (int i = 0; i < 4; i++)
#pragma unroll
        for (int j = 0; j < 8; j++)
#pragma unroll
            for (int c = 0; c < 4; c++) acc[i][j][c] = 0.f;

    auto issue = [&](int kt) {
        const int stage = kt & (NSTAGE - 1);
        const int k0A = kt * 64;
        const int k0B = (kt & 15) * 64;      // W wraps at K=1024
#pragma unroll
        for (int it = 0; it < 12; it++) {
            int idx = tid + it * 256;          // 0..3071
            int isB = idx >= 1024;
            int l   = isB ? (idx - 1024) : idx;
            int row = l >> 3, ch = l & 7;
            const __half* src = isB
                ? W3 + (size_t)(bn + row) * 1024 + k0B + ch * 8
                : A3 + (size_t)(bm + row) * pitchA + k0A + ch * 8;
            uint32_t off = (uint32_t)row * 128 + ch * 16;
            uint32_t dst = sb + stage * STAGE_BYTES + (isB ? 16384 : 0) + swz(off);
            cp16(dst, src);
        }
    };

    issue(0); CP_COMMIT();
    issue(1); CP_COMMIT();
    issue(2); CP_COMMIT();

    const uint32_t rA = wm + (lane & 7) + ((lane >> 3) & 1) * 8;
    const uint32_t kA = ((lane >> 4) & 1) * 16;
    const uint32_t rB = wn + (lane & 7) + ((lane >> 4) & 1) * 8;
    const uint32_t kB = ((lane >> 3) & 1) * 16;

#pragma unroll 1
    for (int kt = 0; kt < KT; kt++) {
        CP_WAIT(2);
        __syncthreads();
        if (kt + 3 < KT) issue(kt + 3);
        CP_COMMIT();

        const uint32_t sA = sb + (kt & (NSTAGE - 1)) * STAGE_BYTES;
        const uint32_t sB = sA + 16384;
#pragma unroll
        for (int ks = 0; ks < 4; ks++) {
            uint32_t a[4][4], b[4][4];
#pragma unroll
            for (int ti = 0; ti < 4; ti++) {
                uint32_t off = (rA + ti * 16) * 128 + ks * 32 + kA;
                LDSM4(a[ti][0], a[ti][1], a[ti][2], a[ti][3], sA + swz(off));
            }
#pragma unroll
            for (int tp = 0; tp < 4; tp++) {
                uint32_t off = (rB + tp * 16) * 128 + ks * 32 + kB;
                LDSM4(b[tp][0], b[tp][1], b[tp][2], b[tp][3], sB + swz(off));
            }
#pragma unroll
            for (int ti = 0; ti < 4; ti++)
#pragma unroll
                for (int tj = 0; tj < 8; tj++)
                    MMA_F16(acc[ti][tj], a[ti], b[tj >> 1][(tj & 1) * 2],
                            b[tj >> 1][(tj & 1) * 2 + 1]);
        }
    }

    // Epilogue
    float* __restrict__ Cout = Js.C[z];
    const float* bias = Js.bias[z];
    const int col0 = bn + wn + (lane & 3) * 2;
    const int r0   = lane >> 2;
#pragma unroll
    for (int ti = 0; ti < 4; ti++) {
        const int row = bm + wm + ti * 16 + r0;
#pragma unroll
        for (int tj = 0; tj < 8; tj++) {
            float2 bv = bias ? *(const float2*)(bias + col0 + tj * 8)
                             : make_float2(0.f, 0.f);
            float2 v0 = make_float2(acc[ti][tj][0] + bv.x, acc[ti][tj][1] + bv.y);
            float2 v1 = make_float2(acc[ti][tj][2] + bv.x, acc[ti][tj][3] + bv.y);
            *(float2*)(Cout + (size_t)row * C_ + col0 + tj * 8)       = v0;
            *(float2*)(Cout + (size_t)(row + 8) * C_ + col0 + tj * 8) = v1;
        }
    }
}

// ---------------------------------------------------------------------------
// Tail V partial sums: 512 blocks (64 bh x 8 parts), each sums 118 rows.
// Sp[bh][part][d] = sum_{r} vp[b, 80+part*118+r, h*64+d]
// ---------------------------------------------------------------------------
__global__ __launch_bounds__(256) void sum_tail_kernel(
    const float* __restrict__ vp, float* __restrict__ Sp)
{
    __shared__ float part[4][D_];
    const int bh   = blockIdx.x;         // 0..63
    const int prt  = blockIdx.y;         // 0..7
    const int b    = bh >> 4, h = bh & 15;
    const int tid  = threadIdx.x;
    const int d = tid & 63, p = tid >> 6;
    const int j0 = WMAX + prt * 118;     // 944 = 8*118
    const size_t base = (size_t)b * T_ * C_ + (size_t)h * D_;
    float s = 0.f;
    for (int r = p; r < 118; r += 4)
        s += vp[base + (size_t)(j0 + r) * C_ + d];
    part[p][d] = s;
    __syncthreads();
    if (tid < D_)
        Sp[(bh * NTAILP + prt) * D_ + tid] =
            part[0][tid] + part[1][tid] + part[2][tid] + part[3][tid];
}

// ---------------------------------------------------------------------------
// Attention: logits nonzero only for j<80; 944 tail logits are exactly 0.
// out[i] = sum_{j<80} a_j * V[j] + (e^{-m}/Z) * S[b,h]
// Block = 128 rows (grid 8x16x4 = 512 CTAs). 1 warp = 16 rows (4 quads).
// Epilogue writes the fp16 2-term split [Oh, Ol] into the P GEMM A-buffer.
// ---------------------------------------------------------------------------
__global__ __launch_bounds__(256) void attn_kernel(
    const float* __restrict__ qp, const float* __restrict__ kp,
    const float* __restrict__ vp, const float* __restrict__ gSp,
    __half* __restrict__ o2)
{
    __shared__ float Vs[WMAX][D_];       // 20 KB
    __shared__ float wbuf[8][4][WMAX];   // 10 KB
    __shared__ float scs[8][4][68];      // 8.5 KB

    const int tid   = threadIdx.x;
    const int lane  = tid & 31;
    const int w     = tid >> 5;
    const int chunk = blockIdx.x;        // 0..7
    const int h     = blockIdx.y;
    const int b     = blockIdx.z;
    const size_t base = (size_t)b * T_ * C_ + (size_t)h * D_;

    for (int idx = tid; idx < WMAX * D_; idx += 256) {
        int j = idx >> 6, d = idx & 63;
        Vs[j][d] = vp[base + (size_t)j * C_ + d];
    }
    __syncthreads();

    // S = sum of 8 tail partials
    float2 S2 = make_float2(0.f, 0.f);
    {
        const float* pp = gSp + (b * H_ + h) * NTAILP * D_ + lane * 2;
#pragma unroll
        for (int p = 0; p < NTAILP; p++) {
            float2 t = *(const float2*)(pp + p * D_);
            S2.x += t.x; S2.y += t.y;
        }
    }

    for (int rq = 0; rq < 4; rq++) {
        const int ibase = chunk * 128 + w * 16 + rq * 4;
        float cr[4];
#pragma unroll
        for (int rr = 0; rr < 4; rr++) {
            const int i = ibase + rr;
            const float2 qv = *(const float2*)(qp + base + (size_t)i * C_ + lane * 2);
            const float2 kv = *(const float2*)(kp + base + (size_t)i * C_ + lane * 2);
            const float p0 = qv.x * kv.x * 0.125f;
            const float p1 = qv.y * kv.y * 0.125f;

            float s = p0 + p1;
#pragma unroll
            for (int off = 1; off < 32; off <<= 1) {
                float t = __shfl_up_sync(0xffffffffu, s, off);
                if (lane >= off) s += t;
            }
            scs[w][rr][2 * lane + 1] = s - p1;
            scs[w][rr][2 * lane + 2] = s;
            if (lane == 0) scs[w][rr][0] = 0.f;
            __syncwarp();

            float wjv[3];
            float m = 0.f;   // includes the 944 exact-zero logits
#pragma unroll
            for (int t3 = 0; t3 < 3; t3++) {
                int j = lane + 32 * t3;
                float wv = -1e30f;
                if (j < WMAX) {
                    int st = (j > 16) ? (j - 16) : 0;
                    int en = (j + 16 < 64) ? (j + 16) : 64;
                    wv = scs[w][rr][en] - scs[w][rr][st];
                    m = fmaxf(m, wv);
                }
                wjv[t3] = wv;
            }
#pragma unroll
            for (int off = 16; off >= 1; off >>= 1)
                m = fmaxf(m, __shfl_xor_sync(0xffffffffu, m, off));

            float zs = 0.f;
#pragma unroll
            for (int t3 = 0; t3 < 3; t3++) {
                int j = lane + 32 * t3;
                if (j < WMAX) {
                    float e = __expf(wjv[t3] - m);
                    zs += e;
                    wjv[t3] = e;
                }
            }
#pragma unroll
            for (int off = 16; off >= 1; off >>= 1)
                zs += __shfl_xor_sync(0xffffffffu, zs, off);

            const float em   = __expf(-m);
            const float invZ = 1.0f / (zs + 944.0f * em);
#pragma unroll
            for (int t3 = 0; t3 < 3; t3++) {
                int j = lane + 32 * t3;
                if (j < WMAX) wbuf[w][rr][j] = wjv[t3] * invZ;
            }
            cr[rr] = em * invZ;
            __syncwarp();
        }

        float2 acc[4];
#pragma unroll
        for (int rr = 0; rr < 4; rr++)
            acc[rr] = make_float2(cr[rr] * S2.x, cr[rr] * S2.y);
#pragma unroll 4
        for (int j = 0; j < WMAX; j++) {
            const float2 vv = *(const float2*)&Vs[j][lane * 2];
#pragma unroll
            for (int rr = 0; rr < 4; rr++) {
                const float aj = wbuf[w][rr][j];
                acc[rr].x = fmaf(aj, vv.x, acc[rr].x);
                acc[rr].y = fmaf(aj, vv.y, acc[rr].y);
            }
        }
#pragma unroll
        for (int rr = 0; rr < 4; rr++) {
            const __half h0 = __float2half_rn(acc[rr].x);
            const __half h1 = __float2half_rn(acc[rr].y);
            const __half l0 = __float2half_rn(acc[rr].x - __half2float(h0));
            const __half l1 = __float2half_rn(acc[rr].y - __half2float(h1));
            const size_t rb = (size_t)(b * T_ + ibase + rr) * 2048 + h * D_ + lane * 2;
            *(__half2*)(o2 + rb)        = __halves2half2(h0, h1);
            *(__half2*)(o2 + rb + 1024) = __halves2half2(l0, l1);
        }
        __syncwarp();
    }
}

// ---------------------------------------------------------------------------
extern "C" void kernel_launch(void* const* d_in, const int* in_sizes, int n_in,
                              void* d_out, int out_size)
{
    const float* q  = (const float*)d_in[0];
    const float* k  = (const float*)d_in[1];
    const float* v  = (const float*)d_in[2];
    const float* Wq = (const float*)d_in[3];
    const float* Wk = (const float*)d_in[4];
    const float* Wv = (const float*)d_in[5];
    const float* Wp = (const float*)d_in[6];
    const float* bp = (const float*)d_in[7];
    float* out = (float*)d_out;

    float *qp, *kp, *vp, *gSp;
    __half *aq, *ak, *av, *ap, *wq, *wk, *wv, *wp;
    cudaGetSymbolAddress((void**)&qp, g_qp);
    cudaGetSymbolAddress((void**)&kp, g_kp);
    cudaGetSymbolAddress((void**)&vp, g_vp);
    cudaGetSymbolAddress((void**)&gSp, g_Sp);
    cudaGetSymbolAddress((void**)&aq, g_aq);
    cudaGetSymbolAddress((void**)&ak, g_ak);
    cudaGetSymbolAddress((void**)&av, g_av);
    cudaGetSymbolAddress((void**)&ap, g_ap);
    cudaGetSymbolAddress((void**)&wq, g_wq);
    cudaGetSymbolAddress((void**)&wk, g_wk);
    cudaGetSymbolAddress((void**)&wv, g_wv);
    cudaGetSymbolAddress((void**)&wp, g_wp);

    cudaFuncSetAttribute(gemm_f16s, cudaFuncAttributeMaxDynamicSharedMemorySize, GEMM_SMEM);

    const int nA4 = MTOT * C_ / 4;   // 1,048,576
    const int nW4 = C_ * C_ / 4;     // 262,144

    // All 7 splits in one launch (weights are all 1-term now):
    SplitJobs J;
    J.src[0] = q;  J.dst[0] = aq; J.n4[0] = nA4; J.pitch[0] = 1024; J.loOff[0] = -1;
    J.src[1] = k;  J.dst[1] = ak; J.n4[1] = nA4; J.pitch[1] = 1024; J.loOff[1] = -1;
    J.src[2] = v;  J.dst[2] = av; J.n4[2] = nA4; J.pitch[2] = 2048; J.loOff[2] = 1024;
    J.src[3] = Wq; J.dst[3] = wq; J.n4[3] = nW4; J.pitch[3] = 1024; J.loOff[3] = -1;
    J.src[4] = Wk; J.dst[4] = wk; J.n4[4] = nW4; J.pitch[4] = 1024; J.loOff[4] = -1;
    J.src[5] = Wv; J.dst[5] = wv; J.n4[5] = nW4; J.pitch[5] = 1024; J.loOff[5] = -1;
    J.src[6] = Wp; J.dst[6] = wp; J.n4[6] = nW4; J.pitch[6] = 1024; J.loOff[6] = -1;
    split_all_kernel<<<dim3(nA4 / 256, 7), 256>>>(J);

    // Fused Q/K/V projections: z=0 is V (long job, scheduled first)
    GemmJobs G;
    G.A[0] = av; G.W[0] = wv; G.bias[0] = nullptr; G.C[0] = vp; G.KT[0] = 32; G.pitchA[0] = 2048;
    G.A[1] = aq; G.W[1] = wq; G.bias[1] = nullptr; G.C[1] = qp; G.KT[1] = 16; G.pitchA[1] = 1024;
    G.A[2] = ak; G.W[2] = wk; G.bias[2] = nullptr; G.C[2] = kp; G.KT[2] = 16; G.pitchA[2] = 1024;
    gemm_f16s<<<dim3(C_ / 256, MTOT / 128, 3), 256, GEMM_SMEM>>>(G);

    sum_tail_kernel<<<dim3(B_ * H_, NTAILP), 256>>>(vp, gSp);

    dim3 ga(T_ / 128, H_, B_);           // 512 CTAs
    attn_kernel<<<ga, 256>>>(qp, kp, vp, gSp, ap);

    // Output projection (+bias), 2-term A, W wraps
    GemmJobs P;
    P.A[0] = ap; P.W[0] = wp; P.bias[0] = bp; P.C[0] = out; P.KT[0] = 32; P.pitchA[0] = 2048;
    P.A[1] = ap; P.W[1] = wp; P.bias[1] = bp; P.C[1] = out; P.KT[1] = 32; P.pitchA[1] = 2048;
    P.A[2] = ap; P.W[2] = wp; P.bias[2] = bp; P.C[2] = out; P.KT[2] = 32; P.pitchA[2] = 2048;
    gemm_f16s<<<dim3(C_ / 256, MTOT / 128, 1), 256, GEMM_SMEM>>>(P);
}